// round 13
// baseline (speedup 1.0000x reference)
#include <cuda_runtime.h>
#include <cuda_bf16.h>
#include <cstdint>

// Problem constants
#define BATCH   2
#define SEQ     2048
#define DMODEL  1024
#define DINNER  2048
#define DSTATE  16
#define DCONV   4
#define MROWS   (BATCH*SEQ)          // 4096

// Scratch (device globals; allocation is forbidden)
__device__ float g_xraw[(size_t)MROWS * DINNER];     // pre-conv xs  [l,d]
__device__ float g_xs[(size_t)MROWS * DINNER];       // post conv+silu [l,d]
__device__ float g_Bp[(size_t)MROWS * DSTATE];       // (xs@W_x)[:,16:32]
__device__ float g_yg[(size_t)MROWS * DINNER];       // gated scan output [l,d]
__device__ float g_WinT[(size_t)(2*DINNER) * DMODEL];  // W_in^T  [4096,1024]
__device__ float g_WdtT[(size_t)DINNER * DINNER];      // W_dt^T  [2048,2048]
__device__ float g_WoutT[(size_t)DMODEL * DINNER];     // W_out^T [1024,2048]
__device__ float g_dT[(size_t)BATCH * DINNER * SEQ];   // delta^T [b,d,l]
__device__ float g_xsT[(size_t)BATCH * DINNER * SEQ];  // xs^T    [b,d,l]
__device__ float g_zT[(size_t)BATCH * DINNER * SEQ];   // z^T     [b,d,l]

// ---------------------------------------------------------------------------
__device__ __forceinline__ uint32_t f2tf32(float f) {
    uint32_t r;
    asm("cvt.rna.tf32.f32 %0, %1;" : "=r"(r) : "f"(f));
    return r;
}

__device__ __forceinline__ void mma_tf32(float c[4],
    uint32_t a0, uint32_t a1, uint32_t a2, uint32_t a3,
    uint32_t b0, uint32_t b1)
{
    asm volatile(
        "mma.sync.aligned.m16n8k8.row.col.f32.tf32.tf32.f32 "
        "{%0,%1,%2,%3}, {%4,%5,%6,%7}, {%8,%9}, {%0,%1,%2,%3};"
        : "+f"(c[0]), "+f"(c[1]), "+f"(c[2]), "+f"(c[3])
        : "r"(a0), "r"(a1), "r"(a2), "r"(a3), "r"(b0), "r"(b1));
}

// ===========================================================================
// TF32 tensor-core GEMM, 512 threads = 16 warps as 4(M) x 4(N), warp tile
// 32x32.  CTA tile 128x128, BK=32, double-buffered smem, fused epilogues.
// MODE 0: plain write to C (ldc).
// MODE 2: split (GEMM1): bn<16 -> plain write into C (ldc); bn>=16 ->
//         transposed write of tile into CT as [b, d, l] (zT).
// MODE 3: softplus(v + bias[col]) then transposed write into CT (dT).
// M%128==0, N%128==0, K%32==0. Row-tiles never straddle a batch.
// ===========================================================================
#define SSTRIDE 36
#define GT_SMEM (2 * 2 * 128 * SSTRIDE * 4)   // 73728 bytes

template <int MODE>
__global__ void __launch_bounds__(512, 1) gemm_tc(
    const float* __restrict__ A, const float* __restrict__ Bt,
    float* __restrict__ C, float* __restrict__ CT,
    int M, int N, int K, int ldc, const float* __restrict__ bias)
{
    extern __shared__ uint32_t sbuf[];   // [2][2][128*SSTRIDE]

    const int tid = threadIdx.x;
    const int wid = tid >> 5, lane = tid & 31;
    const int g  = lane >> 2;        // 0..7
    const int tg = lane & 3;         // 0..3
    const int wm = wid & 3;          // M slot (32 rows each)
    const int wn = wid >> 2;         // N slot (32 cols each)
    const int bm = blockIdx.y, bn = blockIdx.x;

    const float* Ab = A  + (size_t)(bm * 128) * K;
    const float* Bb = Bt + (size_t)(bn * 128) * K;

    float acc[2][4][4];
    #pragma unroll
    for (int i = 0; i < 2; i++)
        #pragma unroll
        for (int j = 0; j < 4; j++)
            #pragma unroll
            for (int f = 0; f < 4; f++) acc[i][j][f] = 0.f;

    const int nchunk = K / 32;

    float4 av[2], bv[2];
    // G2R chunk 0
    #pragma unroll
    for (int i = 0; i < 2; i++) {
        int idx = tid + i * 512;
        int row = idx >> 3, q = idx & 7;
        av[i] = *(const float4*)(Ab + (size_t)row * K + q * 4);
        bv[i] = *(const float4*)(Bb + (size_t)row * K + q * 4);
    }
    // R2S chunk 0 -> buf 0
    #pragma unroll
    for (int i = 0; i < 2; i++) {
        int idx = tid + i * 512;
        int row = idx >> 3, q = idx & 7;
        uint4 ua, ub;
        ua.x = f2tf32(av[i].x); ua.y = f2tf32(av[i].y);
        ua.z = f2tf32(av[i].z); ua.w = f2tf32(av[i].w);
        ub.x = f2tf32(bv[i].x); ub.y = f2tf32(bv[i].y);
        ub.z = f2tf32(bv[i].z); ub.w = f2tf32(bv[i].w);
        *(uint4*)&sbuf[row * SSTRIDE + q * 4] = ua;
        *(uint4*)&sbuf[128 * SSTRIDE + row * SSTRIDE + q * 4] = ub;
    }
    // G2R chunk 1
    if (nchunk > 1) {
        #pragma unroll
        for (int i = 0; i < 2; i++) {
            int idx = tid + i * 512;
            int row = idx >> 3, q = idx & 7;
            av[i] = *(const float4*)(Ab + (size_t)row * K + 32 + q * 4);
            bv[i] = *(const float4*)(Bb + (size_t)row * K + 32 + q * 4);
        }
    }
    __syncthreads();

    for (int c = 0; c < nchunk; c++) {
        // R2S chunk c+1 into buf (c+1)&1
        if (c + 1 < nchunk) {
            uint32_t* base = sbuf + ((c + 1) & 1) * (2 * 128 * SSTRIDE);
            #pragma unroll
            for (int i = 0; i < 2; i++) {
                int idx = tid + i * 512;
                int row = idx >> 3, q = idx & 7;
                uint4 ua, ub;
                ua.x = f2tf32(av[i].x); ua.y = f2tf32(av[i].y);
                ua.z = f2tf32(av[i].z); ua.w = f2tf32(av[i].w);
                ub.x = f2tf32(bv[i].x); ub.y = f2tf32(bv[i].y);
                ub.z = f2tf32(bv[i].z); ub.w = f2tf32(bv[i].w);
                *(uint4*)&base[row * SSTRIDE + q * 4] = ua;
                *(uint4*)&base[128 * SSTRIDE + row * SSTRIDE + q * 4] = ub;
            }
        }
        // G2R chunk c+2
        if (c + 2 < nchunk) {
            int k0n = (c + 2) * 32;
            #pragma unroll
            for (int i = 0; i < 2; i++) {
                int idx = tid + i * 512;
                int row = idx >> 3, q = idx & 7;
                av[i] = *(const float4*)(Ab + (size_t)row * K + k0n + q * 4);
                bv[i] = *(const float4*)(Bb + (size_t)row * K + k0n + q * 4);
            }
        }
        // compute chunk c from buf c&1
        const uint32_t* As = sbuf + (c & 1) * (2 * 128 * SSTRIDE);
        const uint32_t* Bs = As + 128 * SSTRIDE;
        #pragma unroll
        for (int ks = 0; ks < 4; ks++) {
            const int k0 = ks * 8;
            uint32_t af[2][4];
            uint32_t bf[4][2];
            #pragma unroll
            for (int mi = 0; mi < 2; mi++) {
                int mbase = wm * 32 + mi * 16;
                af[mi][0] = As[(mbase + g)     * SSTRIDE + k0 + tg];
                af[mi][1] = As[(mbase + g + 8) * SSTRIDE + k0 + tg];
                af[mi][2] = As[(mbase + g)     * SSTRIDE + k0 + tg + 4];
                af[mi][3] = As[(mbase + g + 8) * SSTRIDE + k0 + tg + 4];
            }
            #pragma unroll
            for (int ni = 0; ni < 4; ni++) {
                int nbase = wn * 32 + ni * 8;
                bf[ni][0] = Bs[(nbase + g) * SSTRIDE + k0 + tg];
                bf[ni][1] = Bs[(nbase + g) * SSTRIDE + k0 + tg + 4];
            }
            #pragma unroll
            for (int mi = 0; mi < 2; mi++)
                #pragma unroll
                for (int ni = 0; ni < 4; ni++)
                    mma_tf32(acc[mi][ni], af[mi][0], af[mi][1], af[mi][2], af[mi][3],
                             bf[ni][0], bf[ni][1]);
        }
        __syncthreads();
    }

    const bool trans = (MODE == 3) || (MODE == 2 && bn >= 16);

    if (!trans) {
        #pragma unroll
        for (int mi = 0; mi < 2; mi++) {
            #pragma unroll
            for (int ni = 0; ni < 4; ni++) {
                int row0 = bm * 128 + wm * 32 + mi * 16 + g;
                int col  = bn * 128 + wn * 32 + ni * 8 + 2 * tg;
                *(float2*)(C + (size_t)row0 * ldc + col) =
                    make_float2(acc[mi][ni][0], acc[mi][ni][1]);
                *(float2*)(C + (size_t)(row0 + 8) * ldc + col) =
                    make_float2(acc[mi][ni][2], acc[mi][ni][3]);
            }
        }
    } else {
        // transposed write via smem staging: st[128 d][132] of l values
        float* st = (float*)sbuf;
        const int d0 = (MODE == 2) ? (bn - 16) * 128 : bn * 128;
        const int bz = bm >> 4;              // SEQ/128 = 16 row-tiles per batch
        const int l0 = (bm & 15) * 128;
        #pragma unroll
        for (int mi = 0; mi < 2; mi++) {
            #pragma unroll
            for (int ni = 0; ni < 4; ni++) {
                int rl = wm * 32 + mi * 16 + g;
                int cl = wn * 32 + ni * 8 + 2 * tg;
                float v0 = acc[mi][ni][0], v1 = acc[mi][ni][1];
                float v2 = acc[mi][ni][2], v3 = acc[mi][ni][3];
                if (MODE == 3) {
                    int col = bn * 128 + cl;
                    float b0 = bias[col], b1 = bias[col + 1];
                    v0 += b0; v1 += b1; v2 += b0; v3 += b1;
                    v0 = (v0 > 20.f) ? v0 : log1pf(__expf(v0));
                    v1 = (v1 > 20.f) ? v1 : log1pf(__expf(v1));
                    v2 = (v2 > 20.f) ? v2 : log1pf(__expf(v2));
                    v3 = (v3 > 20.f) ? v3 : log1pf(__expf(v3));
                }
                st[(cl)     * 132 + rl]     = v0;
                st[(cl + 1) * 132 + rl]     = v1;
                st[(cl)     * 132 + rl + 8] = v2;
                st[(cl + 1) * 132 + rl + 8] = v3;
            }
        }
        __syncthreads();
        #pragma unroll
        for (int i = 0; i < 8; i++) {
            int idx = tid + i * 512;       // 0..4095
            int dl = idx >> 5;             // 0..127
            int c4 = idx & 31;
            float4 v = *(float4*)&st[dl * 132 + c4 * 4];
            *(float4*)&CT[((size_t)bz * DINNER + d0 + dl) * SEQ + l0 + c4 * 4] = v;
        }
    }
}

// ---------------------------------------------------------------------------
// Tiled transpose for weights: out[c][r] = in[r][c].
// ---------------------------------------------------------------------------
__global__ __launch_bounds__(256) void transpose_k(
    const float* __restrict__ in, float* __restrict__ out, int R, int C)
{
    __shared__ float t[32][33];
    int bx = blockIdx.x * 32, by = blockIdx.y * 32;
    int x = bx + threadIdx.x;
    #pragma unroll
    for (int i = 0; i < 32; i += 8)
        t[threadIdx.y + i][threadIdx.x] = in[(size_t)(by + threadIdx.y + i) * C + x];
    __syncthreads();
    x = by + threadIdx.x;
    #pragma unroll
    for (int i = 0; i < 32; i += 8)
        out[(size_t)(bx + threadIdx.y + i) * R + x] = t[threadIdx.x][threadIdx.y + i];
}

// ---------------------------------------------------------------------------
// Tiled depthwise causal conv (width 4) + bias + silu.
// Reads xraw [l,d]. Writes xs [l,d] and xsT [b,d,l].
// ---------------------------------------------------------------------------
__global__ __launch_bounds__(256) void conv_t(
    const float* __restrict__ xraw, const float* __restrict__ cw,
    const float* __restrict__ cb, float* __restrict__ xs,
    float* __restrict__ xsT)
{
    __shared__ float sxin[35][33];
    __shared__ float sy[32][33];
    const int tx = threadIdx.x, ty = threadIdx.y;
    const int d0 = blockIdx.x * 32, l0 = blockIdx.y * 32, b = blockIdx.z;

    #pragma unroll
    for (int i = 0; i < 5; i++) {
        int r = ty + i * 8;
        if (r < 35) {
            int l = l0 + r - 3;
            float v = (l >= 0) ? xraw[((size_t)(b * SEQ + l)) * DINNER + d0 + tx] : 0.f;
            sxin[r][tx] = v;
        }
    }
    __syncthreads();

    const int d = d0 + tx;
    const float w0 = cw[d * 4 + 0], w1 = cw[d * 4 + 1];
    const float w2 = cw[d * 4 + 2], w3 = cw[d * 4 + 3];
    const float bb = cb[d];

    #pragma unroll
    for (int i = 0; i < 4; i++) {
        int r = ty + i * 8;
        float a = bb;
        a = fmaf(w0, sxin[r][tx],     a);
        a = fmaf(w1, sxin[r + 1][tx], a);
        a = fmaf(w2, sxin[r + 2][tx], a);
        a = fmaf(w3, sxin[r + 3][tx], a);
        float val = a / (1.f + __expf(-a));
        sy[r][tx] = val;
        xs[((size_t)(b * SEQ + l0 + r)) * DINNER + d] = val;
    }
    __syncthreads();

    #pragma unroll
    for (int i = 0; i < 4; i++) {
        int dl = ty + i * 8;
        xsT[((size_t)(b * DINNER + d0 + dl)) * SEQ + l0 + tx] = sy[tx][dl];
    }
}

// ---------------------------------------------------------------------------
// Bp[row, s] = sum_d xs[row,d] * W_x[d, 16+s].  32 rows/block, grid 128.
// ---------------------------------------------------------------------------
__global__ __launch_bounds__(256) void bp_k(
    const float* __restrict__ xs, const float* __restrict__ Wx,
    float* __restrict__ Bp)
{
    __shared__ float sx[32][65];
    __shared__ float sw[64][16];
    const int tid = threadIdx.x;
    const int row0 = blockIdx.x * 32;
    const int col = tid & 15;
    const int rbase = (tid >> 4) * 2;

    float acc[2] = {0.f, 0.f};

    for (int k0 = 0; k0 < DINNER; k0 += 64) {
        #pragma unroll
        for (int i = 0; i < 2; i++) {
            int t = tid + i * 256;
            int r = t >> 4;
            int c = (t & 15) << 2;
            float4 v = *(const float4*)&xs[(size_t)(row0 + r) * DINNER + k0 + c];
            sx[r][c + 0] = v.x; sx[r][c + 1] = v.y;
            sx[r][c + 2] = v.z; sx[r][c + 3] = v.w;
        }
        {
            int r = tid >> 2;
            int c = (tid & 3) << 2;
            float4 w = *(const float4*)&Wx[(size_t)(k0 + r) * (2 * DSTATE) + DSTATE + c];
            sw[r][c + 0] = w.x; sw[r][c + 1] = w.y;
            sw[r][c + 2] = w.z; sw[r][c + 3] = w.w;
        }
        __syncthreads();
        #pragma unroll 16
        for (int k = 0; k < 64; k++) {
            float w = sw[k][col];
            acc[0] = fmaf(sx[rbase + 0][k], w, acc[0]);
            acc[1] = fmaf(sx[rbase + 1][k], w, acc[1]);
        }
        __syncthreads();
    }
    Bp[(size_t)(row0 + rbase + 0) * DSTATE + col] = acc[0];
    Bp[(size_t)(row0 + rbase + 1) * DSTATE + col] = acc[1];
}

// ---------------------------------------------------------------------------
// Selective scan v2: channel-major inputs, 16-step smem chunks.
// ---------------------------------------------------------------------------
__global__ __launch_bounds__(256) void scan2_k(
    const float* __restrict__ dT, const float* __restrict__ xsT,
    const float* __restrict__ zT, const float* __restrict__ Bp,
    const float* __restrict__ A_log, const float* __restrict__ Dp,
    float* __restrict__ yg)
{
    __shared__ float sd[16][17], sx[16][17], sz[16][17], sy[16][17];
    __shared__ float sb[16][16];

    const int tid = threadIdx.x;
    const int c = tid >> 4;
    const int s = tid & 15;
    const int ch0 = blockIdx.x * 16;
    const int ch = ch0 + c;
    const int b = ch >> 11;
    const int d = ch & (DINNER - 1);
    const int d0 = ch0 & (DINNER - 1);

    const float A  = -__expf(A_log[d * DSTATE + s]);
    const float Dv = Dp[d];

    const float* dload = dT  + (size_t)(ch0 + c) * SEQ + s;
    const float* xload = xsT + (size_t)(ch0 + c) * SEQ + s;
    const float* zload = zT  + (size_t)(ch0 + c) * SEQ + s;
    const float* bload = Bp + (size_t)b * SEQ * DSTATE + (size_t)c * DSTATE + s;

    float h = 0.f;
    for (int l0 = 0; l0 < SEQ; l0 += 16) {
        sd[c][s] = dload[l0];
        sx[c][s] = xload[l0];
        sz[c][s] = zload[l0];
        sb[c][s] = bload[(size_t)l0 * DSTATE];
        __syncthreads();

        #pragma unroll
        for (int li = 0; li < 16; li++) {
            float dv  = sd[c][li];
            float xv  = sx[c][li];
            float bpv = sb[li][s];
            float dA  = __expf(dv * A);
            h = fmaf(dA, h, dv * xv * bpv);

            float v = h;
            v += __shfl_xor_sync(0xffffffffu, v, 1);
            v += __shfl_xor_sync(0xffffffffu, v, 2);
            v += __shfl_xor_sync(0xffffffffu, v, 4);
            v += __shfl_xor_sync(0xffffffffu, v, 8);

            if (s == 0) {
                float zv = sz[c][li];
                float sig = zv / (1.f + __expf(-zv));
                sy[c][li] = (v + xv * Dv) * sig;
            }
        }
        __syncthreads();

        {
            int sc = tid & 15, sl = tid >> 4;
            yg[(size_t)(b * SEQ + l0 + sl) * DINNER + d0 + sc] = sy[sc][sl];
        }
        __syncthreads();
    }
}

// ---------------------------------------------------------------------------
extern "C" void kernel_launch(void* const* d_in, const int* in_sizes, int n_in,
                              void* d_out, int out_size)
{
    const float* x      = (const float*)d_in[0];
    const float* W_in   = (const float*)d_in[1];
    const float* conv_w = (const float*)d_in[2];
    const float* conv_b = (const float*)d_in[3];
    const float* W_x    = (const float*)d_in[4];
    const float* W_dt   = (const float*)d_in[5];
    const float* b_dt   = (const float*)d_in[6];
    const float* A_log  = (const float*)d_in[7];
    const float* D_par  = (const float*)d_in[8];
    const float* W_out  = (const float*)d_in[9];
    float* out = (float*)d_out;

    float *xraw, *xs, *bp, *yg, *WinT, *WdtT, *WoutT, *dT, *xsT, *zT;
    cudaGetSymbolAddress((void**)&xraw,  g_xraw);
    cudaGetSymbolAddress((void**)&xs,    g_xs);
    cudaGetSymbolAddress((void**)&bp,    g_Bp);
    cudaGetSymbolAddress((void**)&yg,    g_yg);
    cudaGetSymbolAddress((void**)&WinT,  g_WinT);
    cudaGetSymbolAddress((void**)&WdtT,  g_WdtT);
    cudaGetSymbolAddress((void**)&WoutT, g_WoutT);
    cudaGetSymbolAddress((void**)&dT,    g_dT);
    cudaGetSymbolAddress((void**)&xsT,   g_xsT);
    cudaGetSymbolAddress((void**)&zT,    g_zT);

    cudaFuncSetAttribute((const void*)gemm_tc<0>,
                         cudaFuncAttributeMaxDynamicSharedMemorySize, GT_SMEM);
    cudaFuncSetAttribute((const void*)gemm_tc<2>,
                         cudaFuncAttributeMaxDynamicSharedMemorySize, GT_SMEM);
    cudaFuncSetAttribute((const void*)gemm_tc<3>,
                         cudaFuncAttributeMaxDynamicSharedMemorySize, GT_SMEM);

    // 0) transpose weights to [N,K]
    transpose_k<<<dim3((2*DINNER)/32, DMODEL/32), dim3(32, 8)>>>(W_in,  WinT,  DMODEL, 2*DINNER);
    transpose_k<<<dim3(DINNER/32,     DINNER/32), dim3(32, 8)>>>(W_dt,  WdtT,  DINNER, DINNER);
    transpose_k<<<dim3(DMODEL/32,     DINNER/32), dim3(32, 8)>>>(W_out, WoutT, DINNER, DMODEL);

    // 1) x @ W_in: cols 0..2047 -> xraw [l,d]; cols 2048..4095 -> zT [b,d,l]
    gemm_tc<2><<<dim3(32, MROWS/128), 512, GT_SMEM>>>(
        x, WinT, xraw, zT, MROWS, 2*DINNER, DMODEL, DINNER, nullptr);

    // 2) tiled conv+silu -> xs [l,d] and xsT [b,d,l]
    conv_t<<<dim3(DINNER/32, SEQ/32, BATCH), dim3(32, 8)>>>(xraw, conv_w, conv_b, xs, xsT);

    // 3) softplus(xs @ W_dt + b_dt) -> dT [b,d,l] (transposed-only output)
    gemm_tc<3><<<dim3(16, MROWS/128), 512, GT_SMEM>>>(
        xs, WdtT, nullptr, dT, MROWS, DINNER, DINNER, DINNER, b_dt);

    // 3b) Bp = (xs @ W_x)[:, 16:32]
    bp_k<<<MROWS / 32, 256>>>(xs, W_x, bp);

    // 4) selective scan + gating -> yg [l,d]
    scan2_k<<<(BATCH * DINNER) / 16, 256>>>(dT, xsT, zT, bp, A_log, D_par, yg);

    // 5) out = yg @ W_out
    gemm_tc<0><<<dim3(DMODEL/128, MROWS/128), 512, GT_SMEM>>>(
        yg, WoutT, out, nullptr, MROWS, DMODEL, DINNER, DMODEL, nullptr);
}

// round 14
// speedup vs baseline: 1.0760x; 1.0760x over previous
#include <cuda_runtime.h>
#include <cuda_bf16.h>
#include <cstdint>

// Problem constants
#define BATCH   2
#define SEQ     2048
#define DMODEL  1024
#define DINNER  2048
#define DSTATE  16
#define DCONV   4
#define MROWS   (BATCH*SEQ)          // 4096

// Scratch (device globals; allocation is forbidden)
__device__ float g_x32[(size_t)MROWS * DMODEL];      // tf32-truncated x
__device__ float g_xraw[(size_t)MROWS * DINNER];     // pre-conv xs  [l,d]
__device__ float g_xs[(size_t)MROWS * DINNER];       // post conv+silu [l,d] (tf32)
__device__ float g_Bp[(size_t)MROWS * DSTATE];       // (xs@W_x)[:,16:32]
__device__ float g_yg[(size_t)MROWS * DINNER];       // gated scan output [l,d] (tf32)
__device__ float g_WinT[(size_t)(2*DINNER) * DMODEL];  // W_in^T  (tf32)
__device__ float g_WdtT[(size_t)DINNER * DINNER];      // W_dt^T  (tf32)
__device__ float g_WoutT[(size_t)DMODEL * DINNER];     // W_out^T (tf32)
__device__ float g_dT[(size_t)BATCH * DINNER * SEQ];   // delta^T [b,d,l]
__device__ float g_xsT[(size_t)BATCH * DINNER * SEQ];  // xs^T    [b,d,l]
__device__ float g_zT[(size_t)BATCH * DINNER * SEQ];   // z^T     [b,d,l]

// ---------------------------------------------------------------------------
__device__ __forceinline__ uint32_t f2tf32(float f) {
    uint32_t r;
    asm("cvt.rna.tf32.f32 %0, %1;" : "=r"(r) : "f"(f));
    return r;
}
__device__ __forceinline__ float tf32f(float f) { return __uint_as_float(f2tf32(f)); }

__device__ __forceinline__ uint32_t smem_u32(const void* p) {
    uint32_t a;
    asm("{ .reg .u64 t; cvta.to.shared.u64 t, %1; cvt.u32.u64 %0, t; }"
        : "=r"(a) : "l"(p));
    return a;
}

#define CP_ASYNC16(dst_u32, src_ptr) \
    asm volatile("cp.async.cg.shared.global [%0], [%1], 16;" \
        :: "r"(dst_u32), "l"(src_ptr) : "memory")
#define CP_COMMIT() asm volatile("cp.async.commit_group;" ::: "memory")
#define CP_WAIT(n)  asm volatile("cp.async.wait_group %0;" :: "n"(n) : "memory")

__device__ __forceinline__ void mma_tf32(float c[4],
    uint32_t a0, uint32_t a1, uint32_t a2, uint32_t a3,
    uint32_t b0, uint32_t b1)
{
    asm volatile(
        "mma.sync.aligned.m16n8k8.row.col.f32.tf32.tf32.f32 "
        "{%0,%1,%2,%3}, {%4,%5,%6,%7}, {%8,%9}, {%0,%1,%2,%3};"
        : "+f"(c[0]), "+f"(c[1]), "+f"(c[2]), "+f"(c[3])
        : "r"(a0), "r"(a1), "r"(a2), "r"(a3), "r"(b0), "r"(b1));
}

// ===========================================================================
// TF32 tensor-core GEMM: CTA tile 128x256, 256 thr = 8 warps as 2(M) x 4(N),
// warp tile 64x64, BK=32, cp.async double-buffered staging (inputs pre-tf32).
// C[M,N] = A[M,K] @ Bt[N,K]^T.
// MODE 0: plain write to C (ldc).
// MODE 2: bn<8 -> plain write into C (ldc); bn>=8 -> transposed to CT [b,d,l].
// MODE 3: softplus(v + bias[col]) then transposed write into CT.
// M%128==0, N%256==0, K%32==0. Row-tiles never straddle a batch.
// ===========================================================================
#define SSTRIDE 36
#define AWORDS  (128 * SSTRIDE)            // 4608
#define BWORDS  (256 * SSTRIDE)            // 9216
#define BUFWORDS (AWORDS + BWORDS)         // 13824
#define GT_SMEM  (2 * BUFWORDS * 4)        // 110592 bytes (>= epilogue 67584)

template <int MODE>
__global__ void __launch_bounds__(256, 1) gemm_tc(
    const float* __restrict__ A, const float* __restrict__ Bt,
    float* __restrict__ C, float* __restrict__ CT,
    int M, int N, int K, int ldc, const float* __restrict__ bias)
{
    extern __shared__ uint32_t sbuf[];

    const int tid = threadIdx.x;
    const int wid = tid >> 5, lane = tid & 31;
    const int g  = lane >> 2;        // 0..7
    const int tg = lane & 3;         // 0..3
    const int wm = wid & 1;          // M slot (64 rows)
    const int wn = wid >> 1;         // N slot (64 cols)
    const int bm = blockIdx.y, bn = blockIdx.x;

    const float* Ab = A  + (size_t)(bm * 128) * K;
    const float* Bb = Bt + (size_t)(bn * 256) * K;

    const uint32_t sb0 = smem_u32(sbuf);

    float acc[4][8][4];
    #pragma unroll
    for (int i = 0; i < 4; i++)
        #pragma unroll
        for (int j = 0; j < 8; j++)
            #pragma unroll
            for (int f = 0; f < 4; f++) acc[i][j][f] = 0.f;

    const int nchunk = K / 32;

    // issue chunk 0 into buf 0
    {
        #pragma unroll
        for (int i = 0; i < 4; i++) {
            int idx = tid + i * 256;
            int row = idx >> 3, q = idx & 7;
            CP_ASYNC16(sb0 + (uint32_t)(row * SSTRIDE + q * 4) * 4,
                       Ab + (size_t)row * K + q * 4);
        }
        #pragma unroll
        for (int i = 0; i < 8; i++) {
            int idx = tid + i * 256;
            int row = idx >> 3, q = idx & 7;
            CP_ASYNC16(sb0 + (uint32_t)(AWORDS + row * SSTRIDE + q * 4) * 4,
                       Bb + (size_t)row * K + q * 4);
        }
        CP_COMMIT();
    }

    for (int c = 0; c < nchunk; c++) {
        if (c + 1 < nchunk) {
            const uint32_t base = sb0 + (uint32_t)(((c + 1) & 1) * BUFWORDS) * 4;
            const int k0n = (c + 1) * 32;
            #pragma unroll
            for (int i = 0; i < 4; i++) {
                int idx = tid + i * 256;
                int row = idx >> 3, q = idx & 7;
                CP_ASYNC16(base + (uint32_t)(row * SSTRIDE + q * 4) * 4,
                           Ab + (size_t)row * K + k0n + q * 4);
            }
            #pragma unroll
            for (int i = 0; i < 8; i++) {
                int idx = tid + i * 256;
                int row = idx >> 3, q = idx & 7;
                CP_ASYNC16(base + (uint32_t)(AWORDS + row * SSTRIDE + q * 4) * 4,
                           Bb + (size_t)row * K + k0n + q * 4);
            }
            CP_COMMIT();
            CP_WAIT(1);
        } else {
            CP_WAIT(0);
        }
        __syncthreads();

        const uint32_t* As = sbuf + (c & 1) * BUFWORDS;
        const uint32_t* Bs = As + AWORDS;
        #pragma unroll
        for (int ks = 0; ks < 4; ks++) {
            const int k0 = ks * 8;
            uint32_t af[4][4];
            uint32_t bf[8][2];
            #pragma unroll
            for (int mi = 0; mi < 4; mi++) {
                int mbase = wm * 64 + mi * 16;
                af[mi][0] = As[(mbase + g)     * SSTRIDE + k0 + tg];
                af[mi][1] = As[(mbase + g + 8) * SSTRIDE + k0 + tg];
                af[mi][2] = As[(mbase + g)     * SSTRIDE + k0 + tg + 4];
                af[mi][3] = As[(mbase + g + 8) * SSTRIDE + k0 + tg + 4];
            }
            #pragma unroll
            for (int ni = 0; ni < 8; ni++) {
                int nbase = wn * 64 + ni * 8;
                bf[ni][0] = Bs[(nbase + g) * SSTRIDE + k0 + tg];
                bf[ni][1] = Bs[(nbase + g) * SSTRIDE + k0 + tg + 4];
            }
            #pragma unroll
            for (int mi = 0; mi < 4; mi++)
                #pragma unroll
                for (int ni = 0; ni < 8; ni++)
                    mma_tf32(acc[mi][ni], af[mi][0], af[mi][1], af[mi][2], af[mi][3],
                             bf[ni][0], bf[ni][1]);
        }
        __syncthreads();
    }

    const bool trans = (MODE == 3) || (MODE == 2 && bn >= 8);

    if (!trans) {
        #pragma unroll
        for (int mi = 0; mi < 4; mi++) {
            #pragma unroll
            for (int ni = 0; ni < 8; ni++) {
                int row0 = bm * 128 + wm * 64 + mi * 16 + g;
                int col  = bn * 256 + wn * 64 + ni * 8 + 2 * tg;
                *(float2*)(C + (size_t)row0 * ldc + col) =
                    make_float2(acc[mi][ni][0], acc[mi][ni][1]);
                *(float2*)(C + (size_t)(row0 + 8) * ldc + col) =
                    make_float2(acc[mi][ni][2], acc[mi][ni][3]);
            }
        }
    } else {
        // transposed write in two 128-d halves via smem staging st[128][132]
        float* st = (float*)sbuf;
        const int dbase = (MODE == 2) ? (bn - 8) * 256 : bn * 256;
        const int bz = bm >> 4;              // 16 row-tiles per batch
        const int l0 = (bm & 15) * 128;
        #pragma unroll
        for (int half = 0; half < 2; half++) {
            if ((wn >> 1) == half) {
                #pragma unroll
                for (int mi = 0; mi < 4; mi++) {
                    #pragma unroll
                    for (int ni = 0; ni < 8; ni++) {
                        int rl = wm * 64 + mi * 16 + g;
                        int clg = wn * 64 + ni * 8 + 2 * tg;       // 0..255
                        int cl  = clg - half * 128;                 // 0..127
                        float v0 = acc[mi][ni][0], v1 = acc[mi][ni][1];
                        float v2 = acc[mi][ni][2], v3 = acc[mi][ni][3];
                        if (MODE == 3) {
                            int col = bn * 256 + clg;
                            float b0 = bias[col], b1 = bias[col + 1];
                            v0 += b0; v1 += b1; v2 += b0; v3 += b1;
                            v0 = (v0 > 20.f) ? v0 : log1pf(__expf(v0));
                            v1 = (v1 > 20.f) ? v1 : log1pf(__expf(v1));
                            v2 = (v2 > 20.f) ? v2 : log1pf(__expf(v2));
                            v3 = (v3 > 20.f) ? v3 : log1pf(__expf(v3));
                        }
                        st[(cl)     * 132 + rl]     = v0;
                        st[(cl + 1) * 132 + rl]     = v1;
                        st[(cl)     * 132 + rl + 8] = v2;
                        st[(cl + 1) * 132 + rl + 8] = v3;
                    }
                }
            }
            __syncthreads();
            #pragma unroll
            for (int i = 0; i < 16; i++) {
                int idx = tid + i * 256;       // 0..4095
                int dl = idx >> 5;             // 0..127
                int c4 = idx & 31;
                float4 v = *(float4*)&st[dl * 132 + c4 * 4];
                *(float4*)&CT[((size_t)bz * DINNER + dbase + half * 128 + dl) * SEQ
                              + l0 + c4 * 4] = v;
            }
            __syncthreads();
        }
    }
}

// ---------------------------------------------------------------------------
// elementwise tf32 truncation (for x)
// ---------------------------------------------------------------------------
__global__ __launch_bounds__(256) void trunc32_k(
    const float* __restrict__ in, float* __restrict__ out, int n4)
{
    int i = blockIdx.x * blockDim.x + threadIdx.x;
    if (i >= n4) return;
    float4 v = ((const float4*)in)[i];
    v.x = tf32f(v.x); v.y = tf32f(v.y); v.z = tf32f(v.z); v.w = tf32f(v.w);
    ((float4*)out)[i] = v;
}

// ---------------------------------------------------------------------------
// Tiled transpose for weights (+ tf32 truncation): out[c][r] = tf32(in[r][c]).
// ---------------------------------------------------------------------------
__global__ __launch_bounds__(256) void transpose_k(
    const float* __restrict__ in, float* __restrict__ out, int R, int C)
{
    __shared__ float t[32][33];
    int bx = blockIdx.x * 32, by = blockIdx.y * 32;
    int x = bx + threadIdx.x;
    #pragma unroll
    for (int i = 0; i < 32; i += 8)
        t[threadIdx.y + i][threadIdx.x] = in[(size_t)(by + threadIdx.y + i) * C + x];
    __syncthreads();
    x = by + threadIdx.x;
    #pragma unroll
    for (int i = 0; i < 32; i += 8)
        out[(size_t)(bx + threadIdx.y + i) * R + x] = tf32f(t[threadIdx.x][threadIdx.y + i]);
}

// ---------------------------------------------------------------------------
// Tiled depthwise causal conv (width 4) + bias + silu (tf32-truncated output).
// Reads xraw [l,d]. Writes xs [l,d] and xsT [b,d,l].
// ---------------------------------------------------------------------------
__global__ __launch_bounds__(256) void conv_t(
    const float* __restrict__ xraw, const float* __restrict__ cw,
    const float* __restrict__ cb, float* __restrict__ xs,
    float* __restrict__ xsT)
{
    __shared__ float sxin[35][33];
    __shared__ float sy[32][33];
    const int tx = threadIdx.x, ty = threadIdx.y;
    const int d0 = blockIdx.x * 32, l0 = blockIdx.y * 32, b = blockIdx.z;

    #pragma unroll
    for (int i = 0; i < 5; i++) {
        int r = ty + i * 8;
        if (r < 35) {
            int l = l0 + r - 3;
            float v = (l >= 0) ? xraw[((size_t)(b * SEQ + l)) * DINNER + d0 + tx] : 0.f;
            sxin[r][tx] = v;
        }
    }
    __syncthreads();

    const int d = d0 + tx;
    const float w0 = cw[d * 4 + 0], w1 = cw[d * 4 + 1];
    const float w2 = cw[d * 4 + 2], w3 = cw[d * 4 + 3];
    const float bb = cb[d];

    #pragma unroll
    for (int i = 0; i < 4; i++) {
        int r = ty + i * 8;
        float a = bb;
        a = fmaf(w0, sxin[r][tx],     a);
        a = fmaf(w1, sxin[r + 1][tx], a);
        a = fmaf(w2, sxin[r + 2][tx], a);
        a = fmaf(w3, sxin[r + 3][tx], a);
        float val = tf32f(a / (1.f + __expf(-a)));
        sy[r][tx] = val;
        xs[((size_t)(b * SEQ + l0 + r)) * DINNER + d] = val;
    }
    __syncthreads();

    #pragma unroll
    for (int i = 0; i < 4; i++) {
        int dl = ty + i * 8;
        xsT[((size_t)(b * DINNER + d0 + dl)) * SEQ + l0 + tx] = sy[tx][dl];
    }
}

// ---------------------------------------------------------------------------
// Bp[row, s] = sum_d xs[row,d] * W_x[d, 16+s].  32 rows/block, grid 128.
// ---------------------------------------------------------------------------
__global__ __launch_bounds__(256) void bp_k(
    const float* __restrict__ xs, const float* __restrict__ Wx,
    float* __restrict__ Bp)
{
    __shared__ float sx[32][65];
    __shared__ float sw[64][16];
    const int tid = threadIdx.x;
    const int row0 = blockIdx.x * 32;
    const int col = tid & 15;
    const int rbase = (tid >> 4) * 2;

    float acc[2] = {0.f, 0.f};

    for (int k0 = 0; k0 < DINNER; k0 += 64) {
        #pragma unroll
        for (int i = 0; i < 2; i++) {
            int t = tid + i * 256;
            int r = t >> 4;
            int c = (t & 15) << 2;
            float4 v = *(const float4*)&xs[(size_t)(row0 + r) * DINNER + k0 + c];
            sx[r][c + 0] = v.x; sx[r][c + 1] = v.y;
            sx[r][c + 2] = v.z; sx[r][c + 3] = v.w;
        }
        {
            int r = tid >> 2;
            int c = (tid & 3) << 2;
            float4 w = *(const float4*)&Wx[(size_t)(k0 + r) * (2 * DSTATE) + DSTATE + c];
            sw[r][c + 0] = w.x; sw[r][c + 1] = w.y;
            sw[r][c + 2] = w.z; sw[r][c + 3] = w.w;
        }
        __syncthreads();
        #pragma unroll 16
        for (int k = 0; k < 64; k++) {
            float w = sw[k][col];
            acc[0] = fmaf(sx[rbase + 0][k], w, acc[0]);
            acc[1] = fmaf(sx[rbase + 1][k], w, acc[1]);
        }
        __syncthreads();
    }
    Bp[(size_t)(row0 + rbase + 0) * DSTATE + col] = acc[0];
    Bp[(size_t)(row0 + rbase + 1) * DSTATE + col] = acc[1];
}

// ---------------------------------------------------------------------------
// Selective scan v2: channel-major inputs, 16-step smem chunks.
// yg written tf32-truncated (GEMM3 input).
// ---------------------------------------------------------------------------
__global__ __launch_bounds__(256) void scan2_k(
    const float* __restrict__ dT, const float* __restrict__ xsT,
    const float* __restrict__ zT, const float* __restrict__ Bp,
    const float* __restrict__ A_log, const float* __restrict__ Dp,
    float* __restrict__ yg)
{
    __shared__ float sd[16][17], sx[16][17], sz[16][17], sy[16][17];
    __shared__ float sb[16][16];

    const int tid = threadIdx.x;
    const int c = tid >> 4;
    const int s = tid & 15;
    const int ch0 = blockIdx.x * 16;
    const int ch = ch0 + c;
    const int b = ch >> 11;
    const int d = ch & (DINNER - 1);
    const int d0 = ch0 & (DINNER - 1);

    const float A  = -__expf(A_log[d * DSTATE + s]);
    const float Dv = Dp[d];

    const float* dload = dT  + (size_t)(ch0 + c) * SEQ + s;
    const float* xload = xsT + (size_t)(ch0 + c) * SEQ + s;
    const float* zload = zT  + (size_t)(ch0 + c) * SEQ + s;
    const float* bload = Bp + (size_t)b * SEQ * DSTATE + (size_t)c * DSTATE + s;

    float h = 0.f;
    for (int l0 = 0; l0 < SEQ; l0 += 16) {
        sd[c][s] = dload[l0];
        sx[c][s] = xload[l0];
        sz[c][s] = zload[l0];
        sb[c][s] = bload[(size_t)l0 * DSTATE];
        __syncthreads();

        #pragma unroll
        for (int li = 0; li < 16; li++) {
            float dv  = sd[c][li];
            float xv  = sx[c][li];
            float bpv = sb[li][s];
            float dA  = __expf(dv * A);
            h = fmaf(dA, h, dv * xv * bpv);

            float v = h;
            v += __shfl_xor_sync(0xffffffffu, v, 1);
            v += __shfl_xor_sync(0xffffffffu, v, 2);
            v += __shfl_xor_sync(0xffffffffu, v, 4);
            v += __shfl_xor_sync(0xffffffffu, v, 8);

            if (s == 0) {
                float zv = sz[c][li];
                float sig = zv / (1.f + __expf(-zv));
                sy[c][li] = tf32f((v + xv * Dv) * sig);
            }
        }
        __syncthreads();

        {
            int sc = tid & 15, sl = tid >> 4;
            yg[(size_t)(b * SEQ + l0 + sl) * DINNER + d0 + sc] = sy[sc][sl];
        }
        __syncthreads();
    }
}

// ---------------------------------------------------------------------------
extern "C" void kernel_launch(void* const* d_in, const int* in_sizes, int n_in,
                              void* d_out, int out_size)
{
    const float* x      = (const float*)d_in[0];
    const float* W_in   = (const float*)d_in[1];
    const float* conv_w = (const float*)d_in[2];
    const float* conv_b = (const float*)d_in[3];
    const float* W_x    = (const float*)d_in[4];
    const float* W_dt   = (const float*)d_in[5];
    const float* b_dt   = (const float*)d_in[6];
    const float* A_log  = (const float*)d_in[7];
    const float* D_par  = (const float*)d_in[8];
    const float* W_out  = (const float*)d_in[9];
    float* out = (float*)d_out;

    float *x32, *xraw, *xs, *bp, *yg, *WinT, *WdtT, *WoutT, *dT, *xsT, *zT;
    cudaGetSymbolAddress((void**)&x32,   g_x32);
    cudaGetSymbolAddress((void**)&xraw,  g_xraw);
    cudaGetSymbolAddress((void**)&xs,    g_xs);
    cudaGetSymbolAddress((void**)&bp,    g_Bp);
    cudaGetSymbolAddress((void**)&yg,    g_yg);
    cudaGetSymbolAddress((void**)&WinT,  g_WinT);
    cudaGetSymbolAddress((void**)&WdtT,  g_WdtT);
    cudaGetSymbolAddress((void**)&WoutT, g_WoutT);
    cudaGetSymbolAddress((void**)&dT,    g_dT);
    cudaGetSymbolAddress((void**)&xsT,   g_xsT);
    cudaGetSymbolAddress((void**)&zT,    g_zT);

    cudaFuncSetAttribute((const void*)gemm_tc<0>,
                         cudaFuncAttributeMaxDynamicSharedMemorySize, GT_SMEM);
    cudaFuncSetAttribute((const void*)gemm_tc<2>,
                         cudaFuncAttributeMaxDynamicSharedMemorySize, GT_SMEM);
    cudaFuncSetAttribute((const void*)gemm_tc<3>,
                         cudaFuncAttributeMaxDynamicSharedMemorySize, GT_SMEM);

    // 0) tf32-truncate x; transpose weights to [N,K] (tf32)
    trunc32_k<<<(MROWS * DMODEL / 4 + 255) / 256, 256>>>(x, x32, MROWS * DMODEL / 4);
    transpose_k<<<dim3((2*DINNER)/32, DMODEL/32), dim3(32, 8)>>>(W_in,  WinT,  DMODEL, 2*DINNER);
    transpose_k<<<dim3(DINNER/32,     DINNER/32), dim3(32, 8)>>>(W_dt,  WdtT,  DINNER, DINNER);
    transpose_k<<<dim3(DMODEL/32,     DINNER/32), dim3(32, 8)>>>(W_out, WoutT, DINNER, DMODEL);

    // 1) x @ W_in: cols 0..2047 -> xraw [l,d]; cols 2048..4095 -> zT [b,d,l]
    gemm_tc<2><<<dim3(16, MROWS/128), 256, GT_SMEM>>>(
        x32, WinT, xraw, zT, MROWS, 2*DINNER, DMODEL, DINNER, nullptr);

    // 2) tiled conv+silu -> xs [l,d] and xsT [b,d,l] (tf32)
    conv_t<<<dim3(DINNER/32, SEQ/32, BATCH), dim3(32, 8)>>>(xraw, conv_w, conv_b, xs, xsT);

    // 3) softplus(xs @ W_dt + b_dt) -> dT [b,d,l]
    gemm_tc<3><<<dim3(8, MROWS/128), 256, GT_SMEM>>>(
        xs, WdtT, nullptr, dT, MROWS, DINNER, DINNER, DINNER, b_dt);

    // 3b) Bp = (xs @ W_x)[:, 16:32]
    bp_k<<<MROWS / 32, 256>>>(xs, W_x, bp);

    // 4) selective scan + gating -> yg [l,d] (tf32)
    scan2_k<<<(BATCH * DINNER) / 16, 256>>>(dT, xsT, zT, bp, A_log, D_par, yg);

    // 5) out = yg @ W_out
    gemm_tc<0><<<dim3(DMODEL/256, MROWS/128), 256, GT_SMEM>>>(
        yg, WoutT, out, nullptr, MROWS, DMODEL, DINNER, DMODEL, nullptr);
}

// round 15
// speedup vs baseline: 1.0809x; 1.0045x over previous
#include <cuda_runtime.h>
#include <cuda_bf16.h>
#include <cstdint>

// Problem constants
#define BATCH   2
#define SEQ     2048
#define DMODEL  1024
#define DINNER  2048
#define DSTATE  16
#define DCONV   4
#define MROWS   (BATCH*SEQ)          // 4096

// Scratch (device globals; allocation is forbidden)
__device__ float g_x32[(size_t)MROWS * DMODEL];      // tf32-truncated x
__device__ float g_xraw[(size_t)MROWS * DINNER];     // pre-conv xs  [l,d]
__device__ float g_xs[(size_t)MROWS * DINNER];       // post conv+silu [l,d] (tf32)
__device__ float g_Bp[(size_t)MROWS * DSTATE];       // (xs@W_x)[:,16:32]
__device__ float g_yg[(size_t)MROWS * DINNER];       // gated scan output [l,d] (tf32)
__device__ float g_WinT[(size_t)(2*DINNER) * DMODEL];  // W_in^T  (tf32)
__device__ float g_WdtT[(size_t)DINNER * DINNER];      // W_dt^T  (tf32)
__device__ float g_WoutT[(size_t)DMODEL * DINNER];     // W_out^T (tf32)
__device__ float g_dT[(size_t)BATCH * DINNER * SEQ];   // delta^T [b,d,l]
__device__ float g_xsT[(size_t)BATCH * DINNER * SEQ];  // xs^T    [b,d,l]
__device__ float g_zT[(size_t)BATCH * DINNER * SEQ];   // z^T     [b,d,l]

// ---------------------------------------------------------------------------
__device__ __forceinline__ uint32_t f2tf32(float f) {
    uint32_t r;
    asm("cvt.rna.tf32.f32 %0, %1;" : "=r"(r) : "f"(f));
    return r;
}
__device__ __forceinline__ float tf32f(float f) { return __uint_as_float(f2tf32(f)); }

__device__ __forceinline__ uint32_t smem_u32(const void* p) {
    uint32_t a;
    asm("{ .reg .u64 t; cvta.to.shared.u64 t, %1; cvt.u32.u64 %0, t; }"
        : "=r"(a) : "l"(p));
    return a;
}

#define CP_ASYNC16(dst_u32, src_ptr) \
    asm volatile("cp.async.cg.shared.global [%0], [%1], 16;" \
        :: "r"(dst_u32), "l"(src_ptr) : "memory")
#define CP_COMMIT() asm volatile("cp.async.commit_group;" ::: "memory")
#define CP_WAIT(n)  asm volatile("cp.async.wait_group %0;" :: "n"(n) : "memory")

__device__ __forceinline__ void mma_tf32(float c[4],
    uint32_t a0, uint32_t a1, uint32_t a2, uint32_t a3,
    uint32_t b0, uint32_t b1)
{
    asm volatile(
        "mma.sync.aligned.m16n8k8.row.col.f32.tf32.tf32.f32 "
        "{%0,%1,%2,%3}, {%4,%5,%6,%7}, {%8,%9}, {%0,%1,%2,%3};"
        : "+f"(c[0]), "+f"(c[1]), "+f"(c[2]), "+f"(c[3])
        : "r"(a0), "r"(a1), "r"(a2), "r"(a3), "r"(b0), "r"(b1));
}

// ===========================================================================
// TF32 tensor-core GEMM: CTA tile 128x256, 256 thr = 8 warps as 2(M) x 4(N),
// warp tile 64x64, BK=32, cp.async double-buffered staging (inputs pre-tf32).
// MODE 0: plain write to C (ldc).
// MODE 2: bn<8 -> plain write into C (ldc); bn>=8 -> transposed to CT [b,d,l].
// MODE 3: softplus(v + bias[col]) then transposed write into CT.
// ===========================================================================
#define SSTRIDE 36
#define AWORDS  (128 * SSTRIDE)            // 4608
#define BWORDS  (256 * SSTRIDE)            // 9216
#define BUFWORDS (AWORDS + BWORDS)         // 13824
#define GT_SMEM  (2 * BUFWORDS * 4)        // 110592 bytes (>= epilogue 67584)

template <int MODE>
__global__ void __launch_bounds__(256, 1) gemm_tc(
    const float* __restrict__ A, const float* __restrict__ Bt,
    float* __restrict__ C, float* __restrict__ CT,
    int M, int N, int K, int ldc, const float* __restrict__ bias)
{
    extern __shared__ uint32_t sbuf[];

    const int tid = threadIdx.x;
    const int wid = tid >> 5, lane = tid & 31;
    const int g  = lane >> 2;
    const int tg = lane & 3;
    const int wm = wid & 1;          // M slot (64 rows)
    const int wn = wid >> 1;         // N slot (64 cols)
    const int bm = blockIdx.y, bn = blockIdx.x;

    const float* Ab = A  + (size_t)(bm * 128) * K;
    const float* Bb = Bt + (size_t)(bn * 256) * K;

    const uint32_t sb0 = smem_u32(sbuf);

    float acc[4][8][4];
    #pragma unroll
    for (int i = 0; i < 4; i++)
        #pragma unroll
        for (int j = 0; j < 8; j++)
            #pragma unroll
            for (int f = 0; f < 4; f++) acc[i][j][f] = 0.f;

    const int nchunk = K / 32;

    {
        #pragma unroll
        for (int i = 0; i < 4; i++) {
            int idx = tid + i * 256;
            int row = idx >> 3, q = idx & 7;
            CP_ASYNC16(sb0 + (uint32_t)(row * SSTRIDE + q * 4) * 4,
                       Ab + (size_t)row * K + q * 4);
        }
        #pragma unroll
        for (int i = 0; i < 8; i++) {
            int idx = tid + i * 256;
            int row = idx >> 3, q = idx & 7;
            CP_ASYNC16(sb0 + (uint32_t)(AWORDS + row * SSTRIDE + q * 4) * 4,
                       Bb + (size_t)row * K + q * 4);
        }
        CP_COMMIT();
    }

    for (int c = 0; c < nchunk; c++) {
        if (c + 1 < nchunk) {
            const uint32_t base = sb0 + (uint32_t)(((c + 1) & 1) * BUFWORDS) * 4;
            const int k0n = (c + 1) * 32;
            #pragma unroll
            for (int i = 0; i < 4; i++) {
                int idx = tid + i * 256;
                int row = idx >> 3, q = idx & 7;
                CP_ASYNC16(base + (uint32_t)(row * SSTRIDE + q * 4) * 4,
                           Ab + (size_t)row * K + k0n + q * 4);
            }
            #pragma unroll
            for (int i = 0; i < 8; i++) {
                int idx = tid + i * 256;
                int row = idx >> 3, q = idx & 7;
                CP_ASYNC16(base + (uint32_t)(AWORDS + row * SSTRIDE + q * 4) * 4,
                           Bb + (size_t)row * K + k0n + q * 4);
            }
            CP_COMMIT();
            CP_WAIT(1);
        } else {
            CP_WAIT(0);
        }
        __syncthreads();

        const uint32_t* As = sbuf + (c & 1) * BUFWORDS;
        const uint32_t* Bs = As + AWORDS;
        #pragma unroll
        for (int ks = 0; ks < 4; ks++) {
            const int k0 = ks * 8;
            uint32_t af[4][4];
            uint32_t bf[8][2];
            #pragma unroll
            for (int mi = 0; mi < 4; mi++) {
                int mbase = wm * 64 + mi * 16;
                af[mi][0] = As[(mbase + g)     * SSTRIDE + k0 + tg];
                af[mi][1] = As[(mbase + g + 8) * SSTRIDE + k0 + tg];
                af[mi][2] = As[(mbase + g)     * SSTRIDE + k0 + tg + 4];
                af[mi][3] = As[(mbase + g + 8) * SSTRIDE + k0 + tg + 4];
            }
            #pragma unroll
            for (int ni = 0; ni < 8; ni++) {
                int nbase = wn * 64 + ni * 8;
                bf[ni][0] = Bs[(nbase + g) * SSTRIDE + k0 + tg];
                bf[ni][1] = Bs[(nbase + g) * SSTRIDE + k0 + tg + 4];
            }
            #pragma unroll
            for (int mi = 0; mi < 4; mi++)
                #pragma unroll
                for (int ni = 0; ni < 8; ni++)
                    mma_tf32(acc[mi][ni], af[mi][0], af[mi][1], af[mi][2], af[mi][3],
                             bf[ni][0], bf[ni][1]);
        }
        __syncthreads();
    }

    const bool trans = (MODE == 3) || (MODE == 2 && bn >= 8);

    if (!trans) {
        #pragma unroll
        for (int mi = 0; mi < 4; mi++) {
            #pragma unroll
            for (int ni = 0; ni < 8; ni++) {
                int row0 = bm * 128 + wm * 64 + mi * 16 + g;
                int col  = bn * 256 + wn * 64 + ni * 8 + 2 * tg;
                *(float2*)(C + (size_t)row0 * ldc + col) =
                    make_float2(acc[mi][ni][0], acc[mi][ni][1]);
                *(float2*)(C + (size_t)(row0 + 8) * ldc + col) =
                    make_float2(acc[mi][ni][2], acc[mi][ni][3]);
            }
        }
    } else {
        float* st = (float*)sbuf;
        const int dbase = (MODE == 2) ? (bn - 8) * 256 : bn * 256;
        const int bz = bm >> 4;
        const int l0 = (bm & 15) * 128;
        #pragma unroll
        for (int half = 0; half < 2; half++) {
            if ((wn >> 1) == half) {
                #pragma unroll
                for (int mi = 0; mi < 4; mi++) {
                    #pragma unroll
                    for (int ni = 0; ni < 8; ni++) {
                        int rl = wm * 64 + mi * 16 + g;
                        int clg = wn * 64 + ni * 8 + 2 * tg;
                        int cl  = clg - half * 128;
                        float v0 = acc[mi][ni][0], v1 = acc[mi][ni][1];
                        float v2 = acc[mi][ni][2], v3 = acc[mi][ni][3];
                        if (MODE == 3) {
                            int col = bn * 256 + clg;
                            float b0 = bias[col], b1 = bias[col + 1];
                            v0 += b0; v1 += b1; v2 += b0; v3 += b1;
                            v0 = (v0 > 20.f) ? v0 : log1pf(__expf(v0));
                            v1 = (v1 > 20.f) ? v1 : log1pf(__expf(v1));
                            v2 = (v2 > 20.f) ? v2 : log1pf(__expf(v2));
                            v3 = (v3 > 20.f) ? v3 : log1pf(__expf(v3));
                        }
                        st[(cl)     * 132 + rl]     = v0;
                        st[(cl + 1) * 132 + rl]     = v1;
                        st[(cl)     * 132 + rl + 8] = v2;
                        st[(cl + 1) * 132 + rl + 8] = v3;
                    }
                }
            }
            __syncthreads();
            #pragma unroll
            for (int i = 0; i < 16; i++) {
                int idx = tid + i * 256;
                int dl = idx >> 5;
                int c4 = idx & 31;
                float4 v = *(float4*)&st[dl * 132 + c4 * 4];
                *(float4*)&CT[((size_t)bz * DINNER + dbase + half * 128 + dl) * SEQ
                              + l0 + c4 * 4] = v;
            }
            __syncthreads();
        }
    }
}

// ---------------------------------------------------------------------------
// Fused prep: 3 weight transposes (+tf32) and x truncation, one 1D launch.
// tiles: [0,4096) Win | [4096,8192) Wdt | [8192,10240) Wout | [10240,14336) trunc
// ---------------------------------------------------------------------------
__device__ __forceinline__ void transpose_tile(
    const float* __restrict__ in, float* __restrict__ out,
    int R, int C, int xt, int yt, int tid)
{
    __shared__ float t[32][33];
    const int tx = tid & 31, ty = tid >> 5;         // 32 x 8
    const int bx = xt * 32, by = yt * 32;
    #pragma unroll
    for (int i = 0; i < 32; i += 8)
        t[ty + i][tx] = in[(size_t)(by + ty + i) * C + bx + tx];
    __syncthreads();
    #pragma unroll
    for (int i = 0; i < 32; i += 8)
        out[(size_t)(bx + ty + i) * R + by + tx] = tf32f(t[tx][ty + i]);
}

__global__ __launch_bounds__(256) void prep_k(
    const float* __restrict__ W_in,  float* __restrict__ WinT,
    const float* __restrict__ W_dt,  float* __restrict__ WdtT,
    const float* __restrict__ W_out, float* __restrict__ WoutT,
    const float* __restrict__ x,     float* __restrict__ x32)
{
    const int b = blockIdx.x;
    const int tid = threadIdx.x;
    if (b < 4096) {                       // W_in: R=1024, C=4096
        transpose_tile(W_in, WinT, DMODEL, 2 * DINNER, b % 128, b / 128, tid);
    } else if (b < 8192) {                // W_dt: R=2048, C=2048
        int t = b - 4096;
        transpose_tile(W_dt, WdtT, DINNER, DINNER, t % 64, t / 64, tid);
    } else if (b < 10240) {               // W_out: R=2048, C=1024
        int t = b - 8192;
        transpose_tile(W_out, WoutT, DINNER, DMODEL, t % 32, t / 32, tid);
    } else {                              // trunc x: 1M float4 over 4096 blocks
        int i = (b - 10240) * 256 + tid;
        float4 v = ((const float4*)x)[i];
        v.x = tf32f(v.x); v.y = tf32f(v.y); v.z = tf32f(v.z); v.w = tf32f(v.w);
        ((float4*)x32)[i] = v;
    }
}

// ---------------------------------------------------------------------------
// Tiled depthwise causal conv (width 4) + bias + silu (tf32-truncated output).
// ---------------------------------------------------------------------------
__global__ __launch_bounds__(256) void conv_t(
    const float* __restrict__ xraw, const float* __restrict__ cw,
    const float* __restrict__ cb, float* __restrict__ xs,
    float* __restrict__ xsT)
{
    __shared__ float sxin[35][33];
    __shared__ float sy[32][33];
    const int tx = threadIdx.x, ty = threadIdx.y;
    const int d0 = blockIdx.x * 32, l0 = blockIdx.y * 32, b = blockIdx.z;

    #pragma unroll
    for (int i = 0; i < 5; i++) {
        int r = ty + i * 8;
        if (r < 35) {
            int l = l0 + r - 3;
            float v = (l >= 0) ? xraw[((size_t)(b * SEQ + l)) * DINNER + d0 + tx] : 0.f;
            sxin[r][tx] = v;
        }
    }
    __syncthreads();

    const int d = d0 + tx;
    const float w0 = cw[d * 4 + 0], w1 = cw[d * 4 + 1];
    const float w2 = cw[d * 4 + 2], w3 = cw[d * 4 + 3];
    const float bb = cb[d];

    #pragma unroll
    for (int i = 0; i < 4; i++) {
        int r = ty + i * 8;
        float a = bb;
        a = fmaf(w0, sxin[r][tx],     a);
        a = fmaf(w1, sxin[r + 1][tx], a);
        a = fmaf(w2, sxin[r + 2][tx], a);
        a = fmaf(w3, sxin[r + 3][tx], a);
        float val = tf32f(a / (1.f + __expf(-a)));
        sy[r][tx] = val;
        xs[((size_t)(b * SEQ + l0 + r)) * DINNER + d] = val;
    }
    __syncthreads();

    #pragma unroll
    for (int i = 0; i < 4; i++) {
        int dl = ty + i * 8;
        xsT[((size_t)(b * DINNER + d0 + dl)) * SEQ + l0 + tx] = sy[tx][dl];
    }
}

// ---------------------------------------------------------------------------
// Bp[row, s] = sum_d xs[row,d] * W_x[d, 16+s].  16 rows/block, grid 256.
// ---------------------------------------------------------------------------
__global__ __launch_bounds__(256) void bp_k(
    const float* __restrict__ xs, const float* __restrict__ Wx,
    float* __restrict__ Bp)
{
    __shared__ float sx[16][65];
    __shared__ float sw[64][16];
    const int tid = threadIdx.x;
    const int row0 = blockIdx.x * 16;
    const int col = tid & 15;
    const int row = tid >> 4;        // 0..15

    float acc = 0.f;

    for (int k0 = 0; k0 < DINNER; k0 += 64) {
        {
            int r = tid >> 4;
            int c = (tid & 15) << 2;
            float4 v = *(const float4*)&xs[(size_t)(row0 + r) * DINNER + k0 + c];
            sx[r][c + 0] = v.x; sx[r][c + 1] = v.y;
            sx[r][c + 2] = v.z; sx[r][c + 3] = v.w;
        }
        {
            int r = tid >> 2;
            int c = (tid & 3) << 2;
            float4 w = *(const float4*)&Wx[(size_t)(k0 + r) * (2 * DSTATE) + DSTATE + c];
            sw[r][c + 0] = w.x; sw[r][c + 1] = w.y;
            sw[r][c + 2] = w.z; sw[r][c + 3] = w.w;
        }
        __syncthreads();
        #pragma unroll 16
        for (int k = 0; k < 64; k++)
            acc = fmaf(sx[row][k], sw[k][col], acc);
        __syncthreads();
    }
    Bp[(size_t)(row0 + row) * DSTATE + col] = acc;
}

// ---------------------------------------------------------------------------
// Selective scan v2: channel-major inputs, 16-step smem chunks, 2 syncs/chunk
// (sy double-buffered). yg written tf32-truncated (GEMM3 input).
// ---------------------------------------------------------------------------
__global__ __launch_bounds__(256) void scan2_k(
    const float* __restrict__ dT, const float* __restrict__ xsT,
    const float* __restrict__ zT, const float* __restrict__ Bp,
    const float* __restrict__ A_log, const float* __restrict__ Dp,
    float* __restrict__ yg)
{
    __shared__ float sd[16][17], sx[16][17], sz[16][17];
    __shared__ float sy[2][16][17];
    __shared__ float sb[16][16];

    const int tid = threadIdx.x;
    const int c = tid >> 4;
    const int s = tid & 15;
    const int ch0 = blockIdx.x * 16;
    const int ch = ch0 + c;
    const int b = ch >> 11;
    const int d = ch & (DINNER - 1);
    const int d0 = ch0 & (DINNER - 1);

    const float A  = -__expf(A_log[d * DSTATE + s]);
    const float Dv = Dp[d];

    const float* dload = dT  + (size_t)(ch0 + c) * SEQ + s;
    const float* xload = xsT + (size_t)(ch0 + c) * SEQ + s;
    const float* zload = zT  + (size_t)(ch0 + c) * SEQ + s;
    const float* bload = Bp + (size_t)b * SEQ * DSTATE + (size_t)c * DSTATE + s;

    const int sc = tid & 15, sl = tid >> 4;

    float h = 0.f;
    for (int l0 = 0; l0 < SEQ; l0 += 16) {
        const int p = (l0 >> 4) & 1;
        sd[c][s] = dload[l0];
        sx[c][s] = xload[l0];
        sz[c][s] = zload[l0];
        sb[c][s] = bload[(size_t)l0 * DSTATE];
        __syncthreads();

        #pragma unroll
        for (int li = 0; li < 16; li++) {
            float dv  = sd[c][li];
            float xv  = sx[c][li];
            float bpv = sb[li][s];
            float dA  = __expf(dv * A);
            h = fmaf(dA, h, dv * xv * bpv);

            float v = h;
            v += __shfl_xor_sync(0xffffffffu, v, 1);
            v += __shfl_xor_sync(0xffffffffu, v, 2);
            v += __shfl_xor_sync(0xffffffffu, v, 4);
            v += __shfl_xor_sync(0xffffffffu, v, 8);

            if (s == 0) {
                float zv = sz[c][li];
                float sig = zv / (1.f + __expf(-zv));
                sy[p][c][li] = tf32f((v + xv * Dv) * sig);
            }
        }
        __syncthreads();

        yg[(size_t)(b * SEQ + l0 + sl) * DINNER + d0 + sc] = sy[p][sc][sl];
        // no third sync: next chunk writes sd/sx/sz (disjoint) and sy[1-p]
    }
}

// ---------------------------------------------------------------------------
extern "C" void kernel_launch(void* const* d_in, const int* in_sizes, int n_in,
                              void* d_out, int out_size)
{
    const float* x      = (const float*)d_in[0];
    const float* W_in   = (const float*)d_in[1];
    const float* conv_w = (const float*)d_in[2];
    const float* conv_b = (const float*)d_in[3];
    const float* W_x    = (const float*)d_in[4];
    const float* W_dt   = (const float*)d_in[5];
    const float* b_dt   = (const float*)d_in[6];
    const float* A_log  = (const float*)d_in[7];
    const float* D_par  = (const float*)d_in[8];
    const float* W_out  = (const float*)d_in[9];
    float* out = (float*)d_out;

    float *x32, *xraw, *xs, *bp, *yg, *WinT, *WdtT, *WoutT, *dT, *xsT, *zT;
    cudaGetSymbolAddress((void**)&x32,   g_x32);
    cudaGetSymbolAddress((void**)&xraw,  g_xraw);
    cudaGetSymbolAddress((void**)&xs,    g_xs);
    cudaGetSymbolAddress((void**)&bp,    g_Bp);
    cudaGetSymbolAddress((void**)&yg,    g_yg);
    cudaGetSymbolAddress((void**)&WinT,  g_WinT);
    cudaGetSymbolAddress((void**)&WdtT,  g_WdtT);
    cudaGetSymbolAddress((void**)&WoutT, g_WoutT);
    cudaGetSymbolAddress((void**)&dT,    g_dT);
    cudaGetSymbolAddress((void**)&xsT,   g_xsT);
    cudaGetSymbolAddress((void**)&zT,    g_zT);

    cudaFuncSetAttribute((const void*)gemm_tc<0>,
                         cudaFuncAttributeMaxDynamicSharedMemorySize, GT_SMEM);
    cudaFuncSetAttribute((const void*)gemm_tc<2>,
                         cudaFuncAttributeMaxDynamicSharedMemorySize, GT_SMEM);
    cudaFuncSetAttribute((const void*)gemm_tc<3>,
                         cudaFuncAttributeMaxDynamicSharedMemorySize, GT_SMEM);

    // 1) fused prep: weight transposes (tf32) + x truncation
    prep_k<<<14336, 256>>>(W_in, WinT, W_dt, WdtT, W_out, WoutT, x, x32);

    // 2) x @ W_in: cols 0..2047 -> xraw [l,d]; cols 2048..4095 -> zT [b,d,l]
    gemm_tc<2><<<dim3(16, MROWS/128), 256, GT_SMEM>>>(
        x32, WinT, xraw, zT, MROWS, 2*DINNER, DMODEL, DINNER, nullptr);

    // 3) tiled conv+silu -> xs [l,d] and xsT [b,d,l] (tf32)
    conv_t<<<dim3(DINNER/32, SEQ/32, BATCH), dim3(32, 8)>>>(xraw, conv_w, conv_b, xs, xsT);

    // 4) softplus(xs @ W_dt + b_dt) -> dT [b,d,l]   (launch slot 4 -> profiled)
    gemm_tc<3><<<dim3(8, MROWS/128), 256, GT_SMEM>>>(
        xs, WdtT, nullptr, dT, MROWS, DINNER, DINNER, DINNER, b_dt);

    // 5) Bp = (xs @ W_x)[:, 16:32]
    bp_k<<<MROWS / 16, 256>>>(xs, W_x, bp);

    // 6) selective scan + gating -> yg [l,d] (tf32)
    scan2_k<<<(BATCH * DINNER) / 16, 256>>>(dT, xsT, zT, bp, A_log, D_par, yg);

    // 7) out = yg @ W_out
    gemm_tc<0><<<dim3(DMODEL/256, MROWS/128), 256, GT_SMEM>>>(
        yg, WoutT, out, nullptr, MROWS, DMODEL, DINNER, DMODEL, nullptr);
}

// round 16
// speedup vs baseline: 1.1127x; 1.0294x over previous
#include <cuda_runtime.h>
#include <cuda_bf16.h>
#include <cstdint>

// Problem constants
#define BATCH   2
#define SEQ     2048
#define DMODEL  1024
#define DINNER  2048
#define DSTATE  16
#define DCONV   4
#define MROWS   (BATCH*SEQ)          // 4096

// Scratch (device globals; allocation is forbidden)
__device__ float g_x32[(size_t)MROWS * DMODEL];      // tf32-truncated x
__device__ float g_xraw[(size_t)MROWS * DINNER];     // pre-conv xs  [l,d]
__device__ float g_xs[(size_t)MROWS * DINNER];       // post conv+silu [l,d] (tf32)
__device__ float g_Bp[(size_t)MROWS * DSTATE];       // (xs@W_x)[:,16:32]
__device__ float g_yg[(size_t)MROWS * DINNER];       // gated scan output [l,d] (tf32)
__device__ float g_WinT[(size_t)(2*DINNER) * DMODEL];  // W_in^T  (tf32)
__device__ float g_WdtT[(size_t)DINNER * DINNER];      // W_dt^T  (tf32)
__device__ float g_WoutT[(size_t)DMODEL * DINNER];     // W_out^T (tf32)
__device__ float g_dT[(size_t)BATCH * DINNER * SEQ];   // delta^T [b,d,l]
__device__ float g_xsT[(size_t)BATCH * DINNER * SEQ];  // xs^T    [b,d,l]
__device__ float g_zT[(size_t)BATCH * DINNER * SEQ];   // z^T     [b,d,l]

// ---------------------------------------------------------------------------
__device__ __forceinline__ uint32_t f2tf32(float f) {
    uint32_t r;
    asm("cvt.rna.tf32.f32 %0, %1;" : "=r"(r) : "f"(f));
    return r;
}
__device__ __forceinline__ float tf32f(float f) { return __uint_as_float(f2tf32(f)); }

__device__ __forceinline__ uint32_t smem_u32(const void* p) {
    uint32_t a;
    asm("{ .reg .u64 t; cvta.to.shared.u64 t, %1; cvt.u32.u64 %0, t; }"
        : "=r"(a) : "l"(p));
    return a;
}

#define CP_ASYNC16(dst_u32, src_ptr) \
    asm volatile("cp.async.cg.shared.global [%0], [%1], 16;" \
        :: "r"(dst_u32), "l"(src_ptr) : "memory")
#define CP_COMMIT() asm volatile("cp.async.commit_group;" ::: "memory")
#define CP_WAIT(n)  asm volatile("cp.async.wait_group %0;" :: "n"(n) : "memory")

__device__ __forceinline__ void mma_tf32(float c[4],
    uint32_t a0, uint32_t a1, uint32_t a2, uint32_t a3,
    uint32_t b0, uint32_t b1)
{
    asm volatile(
        "mma.sync.aligned.m16n8k8.row.col.f32.tf32.tf32.f32 "
        "{%0,%1,%2,%3}, {%4,%5,%6,%7}, {%8,%9}, {%0,%1,%2,%3};"
        : "+f"(c[0]), "+f"(c[1]), "+f"(c[2]), "+f"(c[3])
        : "r"(a0), "r"(a1), "r"(a2), "r"(a3), "r"(b0), "r"(b1));
}

// ===========================================================================
// TF32 tensor-core GEMM: CTA tile 128x256, 512 thr = 16 warps as 2(M) x 8(N),
// warp tile 64x32, BK=32, cp.async double-buffered staging (inputs pre-tf32).
// MODE 0: plain write to C (ldc).
// MODE 2: bn<8 -> plain write into C (ldc); bn>=8 -> transposed to CT [b,d,l].
// MODE 3: softplus(v + bias[col]) then transposed write into CT.
// ===========================================================================
#define SSTRIDE 36
#define AWORDS  (128 * SSTRIDE)            // 4608
#define BWORDS  (256 * SSTRIDE)            // 9216
#define BUFWORDS (AWORDS + BWORDS)         // 13824
#define GT_SMEM  (2 * BUFWORDS * 4)        // 110592 bytes (>= epilogue 67584)

template <int MODE>
__global__ void __launch_bounds__(512, 1) gemm_tc(
    const float* __restrict__ A, const float* __restrict__ Bt,
    float* __restrict__ C, float* __restrict__ CT,
    int M, int N, int K, int ldc, const float* __restrict__ bias)
{
    extern __shared__ uint32_t sbuf[];

    const int tid = threadIdx.x;
    const int wid = tid >> 5, lane = tid & 31;
    const int g  = lane >> 2;
    const int tg = lane & 3;
    const int wm = wid & 1;          // M slot (64 rows)
    const int wn = wid >> 1;         // N slot (32 cols), 0..7
    const int bm = blockIdx.y, bn = blockIdx.x;

    const float* Ab = A  + (size_t)(bm * 128) * K;
    const float* Bb = Bt + (size_t)(bn * 256) * K;

    const uint32_t sb0 = smem_u32(sbuf);

    float acc[4][4][4];
    #pragma unroll
    for (int i = 0; i < 4; i++)
        #pragma unroll
        for (int j = 0; j < 4; j++)
            #pragma unroll
            for (int f = 0; f < 4; f++) acc[i][j][f] = 0.f;

    const int nchunk = K / 32;

    {
        #pragma unroll
        for (int i = 0; i < 2; i++) {
            int idx = tid + i * 512;
            int row = idx >> 3, q = idx & 7;
            CP_ASYNC16(sb0 + (uint32_t)(row * SSTRIDE + q * 4) * 4,
                       Ab + (size_t)row * K + q * 4);
        }
        #pragma unroll
        for (int i = 0; i < 4; i++) {
            int idx = tid + i * 512;
            int row = idx >> 3, q = idx & 7;
            CP_ASYNC16(sb0 + (uint32_t)(AWORDS + row * SSTRIDE + q * 4) * 4,
                       Bb + (size_t)row * K + q * 4);
        }
        CP_COMMIT();
    }

    for (int c = 0; c < nchunk; c++) {
        if (c + 1 < nchunk) {
            const uint32_t base = sb0 + (uint32_t)(((c + 1) & 1) * BUFWORDS) * 4;
            const int k0n = (c + 1) * 32;
            #pragma unroll
            for (int i = 0; i < 2; i++) {
                int idx = tid + i * 512;
                int row = idx >> 3, q = idx & 7;
                CP_ASYNC16(base + (uint32_t)(row * SSTRIDE + q * 4) * 4,
                           Ab + (size_t)row * K + k0n + q * 4);
            }
            #pragma unroll
            for (int i = 0; i < 4; i++) {
                int idx = tid + i * 512;
                int row = idx >> 3, q = idx & 7;
                CP_ASYNC16(base + (uint32_t)(AWORDS + row * SSTRIDE + q * 4) * 4,
                           Bb + (size_t)row * K + k0n + q * 4);
            }
            CP_COMMIT();
            CP_WAIT(1);
        } else {
            CP_WAIT(0);
        }
        __syncthreads();

        const uint32_t* As = sbuf + (c & 1) * BUFWORDS;
        const uint32_t* Bs = As + AWORDS;
        #pragma unroll
        for (int ks = 0; ks < 4; ks++) {
            const int k0 = ks * 8;
            uint32_t af[4][4];
            uint32_t bf[4][2];
            #pragma unroll
            for (int mi = 0; mi < 4; mi++) {
                int mbase = wm * 64 + mi * 16;
                af[mi][0] = As[(mbase + g)     * SSTRIDE + k0 + tg];
                af[mi][1] = As[(mbase + g + 8) * SSTRIDE + k0 + tg];
                af[mi][2] = As[(mbase + g)     * SSTRIDE + k0 + tg + 4];
                af[mi][3] = As[(mbase + g + 8) * SSTRIDE + k0 + tg + 4];
            }
            #pragma unroll
            for (int ni = 0; ni < 4; ni++) {
                int nbase = wn * 32 + ni * 8;
                bf[ni][0] = Bs[(nbase + g) * SSTRIDE + k0 + tg];
                bf[ni][1] = Bs[(nbase + g) * SSTRIDE + k0 + tg + 4];
            }
            #pragma unroll
            for (int mi = 0; mi < 4; mi++)
                #pragma unroll
                for (int ni = 0; ni < 4; ni++)
                    mma_tf32(acc[mi][ni], af[mi][0], af[mi][1], af[mi][2], af[mi][3],
                             bf[ni][0], bf[ni][1]);
        }
        __syncthreads();
    }

    const bool trans = (MODE == 3) || (MODE == 2 && bn >= 8);

    if (!trans) {
        #pragma unroll
        for (int mi = 0; mi < 4; mi++) {
            #pragma unroll
            for (int ni = 0; ni < 4; ni++) {
                int row0 = bm * 128 + wm * 64 + mi * 16 + g;
                int col  = bn * 256 + wn * 32 + ni * 8 + 2 * tg;
                *(float2*)(C + (size_t)row0 * ldc + col) =
                    make_float2(acc[mi][ni][0], acc[mi][ni][1]);
                *(float2*)(C + (size_t)(row0 + 8) * ldc + col) =
                    make_float2(acc[mi][ni][2], acc[mi][ni][3]);
            }
        }
    } else {
        float* st = (float*)sbuf;
        const int dbase = (MODE == 2) ? (bn - 8) * 256 : bn * 256;
        const int bz = bm >> 4;
        const int l0 = (bm & 15) * 128;
        #pragma unroll
        for (int half = 0; half < 2; half++) {
            if ((wn >> 2) == half) {
                #pragma unroll
                for (int mi = 0; mi < 4; mi++) {
                    #pragma unroll
                    for (int ni = 0; ni < 4; ni++) {
                        int rl = wm * 64 + mi * 16 + g;
                        int clg = wn * 32 + ni * 8 + 2 * tg;       // 0..255
                        int cl  = clg - half * 128;                 // 0..127
                        float v0 = acc[mi][ni][0], v1 = acc[mi][ni][1];
                        float v2 = acc[mi][ni][2], v3 = acc[mi][ni][3];
                        if (MODE == 3) {
                            int col = bn * 256 + clg;
                            float b0 = bias[col], b1 = bias[col + 1];
                            v0 += b0; v1 += b1; v2 += b0; v3 += b1;
                            v0 = (v0 > 20.f) ? v0 : log1pf(__expf(v0));
                            v1 = (v1 > 20.f) ? v1 : log1pf(__expf(v1));
                            v2 = (v2 > 20.f) ? v2 : log1pf(__expf(v2));
                            v3 = (v3 > 20.f) ? v3 : log1pf(__expf(v3));
                        }
                        st[(cl)     * 132 + rl]     = v0;
                        st[(cl + 1) * 132 + rl]     = v1;
                        st[(cl)     * 132 + rl + 8] = v2;
                        st[(cl + 1) * 132 + rl + 8] = v3;
                    }
                }
            }
            __syncthreads();
            #pragma unroll
            for (int i = 0; i < 8; i++) {
                int idx = tid + i * 512;       // 0..4095
                int dl = idx >> 5;
                int c4 = idx & 31;
                float4 v = *(float4*)&st[dl * 132 + c4 * 4];
                *(float4*)&CT[((size_t)bz * DINNER + dbase + half * 128 + dl) * SEQ
                              + l0 + c4 * 4] = v;
            }
            __syncthreads();
        }
    }
}

// ---------------------------------------------------------------------------
// Fused prep: 3 weight transposes (+tf32) and x truncation, one 1D launch.
// ---------------------------------------------------------------------------
__device__ __forceinline__ void transpose_tile(
    const float* __restrict__ in, float* __restrict__ out,
    int R, int C, int xt, int yt, int tid)
{
    __shared__ float t[32][33];
    const int tx = tid & 31, ty = tid >> 5;
    const int bx = xt * 32, by = yt * 32;
    #pragma unroll
    for (int i = 0; i < 32; i += 8)
        t[ty + i][tx] = in[(size_t)(by + ty + i) * C + bx + tx];
    __syncthreads();
    #pragma unroll
    for (int i = 0; i < 32; i += 8)
        out[(size_t)(bx + ty + i) * R + by + tx] = tf32f(t[tx][ty + i]);
}

__global__ __launch_bounds__(256) void prep_k(
    const float* __restrict__ W_in,  float* __restrict__ WinT,
    const float* __restrict__ W_dt,  float* __restrict__ WdtT,
    const float* __restrict__ W_out, float* __restrict__ WoutT,
    const float* __restrict__ x,     float* __restrict__ x32)
{
    const int b = blockIdx.x;
    const int tid = threadIdx.x;
    if (b < 4096) {
        transpose_tile(W_in, WinT, DMODEL, 2 * DINNER, b % 128, b / 128, tid);
    } else if (b < 8192) {
        int t = b - 4096;
        transpose_tile(W_dt, WdtT, DINNER, DINNER, t % 64, t / 64, tid);
    } else if (b < 10240) {
        int t = b - 8192;
        transpose_tile(W_out, WoutT, DINNER, DMODEL, t % 32, t / 32, tid);
    } else {
        int i = (b - 10240) * 256 + tid;
        float4 v = ((const float4*)x)[i];
        v.x = tf32f(v.x); v.y = tf32f(v.y); v.z = tf32f(v.z); v.w = tf32f(v.w);
        ((float4*)x32)[i] = v;
    }
}

// ---------------------------------------------------------------------------
// Tiled depthwise causal conv (width 4) + bias + silu (tf32-truncated output).
// ---------------------------------------------------------------------------
__global__ __launch_bounds__(256) void conv_t(
    const float* __restrict__ xraw, const float* __restrict__ cw,
    const float* __restrict__ cb, float* __restrict__ xs,
    float* __restrict__ xsT)
{
    __shared__ float sxin[35][33];
    __shared__ float sy[32][33];
    const int tx = threadIdx.x, ty = threadIdx.y;
    const int d0 = blockIdx.x * 32, l0 = blockIdx.y * 32, b = blockIdx.z;

    #pragma unroll
    for (int i = 0; i < 5; i++) {
        int r = ty + i * 8;
        if (r < 35) {
            int l = l0 + r - 3;
            float v = (l >= 0) ? xraw[((size_t)(b * SEQ + l)) * DINNER + d0 + tx] : 0.f;
            sxin[r][tx] = v;
        }
    }
    __syncthreads();

    const int d = d0 + tx;
    const float w0 = cw[d * 4 + 0], w1 = cw[d * 4 + 1];
    const float w2 = cw[d * 4 + 2], w3 = cw[d * 4 + 3];
    const float bb = cb[d];

    #pragma unroll
    for (int i = 0; i < 4; i++) {
        int r = ty + i * 8;
        float a = bb;
        a = fmaf(w0, sxin[r][tx],     a);
        a = fmaf(w1, sxin[r + 1][tx], a);
        a = fmaf(w2, sxin[r + 2][tx], a);
        a = fmaf(w3, sxin[r + 3][tx], a);
        float val = tf32f(a / (1.f + __expf(-a)));
        sy[r][tx] = val;
        xs[((size_t)(b * SEQ + l0 + r)) * DINNER + d] = val;
    }
    __syncthreads();

    #pragma unroll
    for (int i = 0; i < 4; i++) {
        int dl = ty + i * 8;
        xsT[((size_t)(b * DINNER + d0 + dl)) * SEQ + l0 + tx] = sy[tx][dl];
    }
}

// ---------------------------------------------------------------------------
// Bp[row, s] = sum_d xs[row,d] * W_x[d, 16+s].  16 rows/block, grid 256.
// ---------------------------------------------------------------------------
__global__ __launch_bounds__(256) void bp_k(
    const float* __restrict__ xs, const float* __restrict__ Wx,
    float* __restrict__ Bp)
{
    __shared__ float sx[16][65];
    __shared__ float sw[64][16];
    const int tid = threadIdx.x;
    const int row0 = blockIdx.x * 16;
    const int col = tid & 15;
    const int row = tid >> 4;

    float acc = 0.f;

    for (int k0 = 0; k0 < DINNER; k0 += 64) {
        {
            int r = tid >> 4;
            int c = (tid & 15) << 2;
            float4 v = *(const float4*)&xs[(size_t)(row0 + r) * DINNER + k0 + c];
            sx[r][c + 0] = v.x; sx[r][c + 1] = v.y;
            sx[r][c + 2] = v.z; sx[r][c + 3] = v.w;
        }
        {
            int r = tid >> 2;
            int c = (tid & 3) << 2;
            float4 w = *(const float4*)&Wx[(size_t)(k0 + r) * (2 * DSTATE) + DSTATE + c];
            sw[r][c + 0] = w.x; sw[r][c + 1] = w.y;
            sw[r][c + 2] = w.z; sw[r][c + 3] = w.w;
        }
        __syncthreads();
        #pragma unroll 16
        for (int k = 0; k < 64; k++)
            acc = fmaf(sx[row][k], sw[k][col], acc);
        __syncthreads();
    }
    Bp[(size_t)(row0 + row) * DSTATE + col] = acc;
}

// ---------------------------------------------------------------------------
// Selective scan v2: channel-major inputs, 16-step smem chunks, 2 syncs/chunk.
// ---------------------------------------------------------------------------
__global__ __launch_bounds__(256) void scan2_k(
    const float* __restrict__ dT, const float* __restrict__ xsT,
    const float* __restrict__ zT, const float* __restrict__ Bp,
    const float* __restrict__ A_log, const float* __restrict__ Dp,
    float* __restrict__ yg)
{
    __shared__ float sd[16][17], sx[16][17], sz[16][17];
    __shared__ float sy[2][16][17];
    __shared__ float sb[16][16];

    const int tid = threadIdx.x;
    const int c = tid >> 4;
    const int s = tid & 15;
    const int ch0 = blockIdx.x * 16;
    const int ch = ch0 + c;
    const int b = ch >> 11;
    const int d = ch & (DINNER - 1);
    const int d0 = ch0 & (DINNER - 1);

    const float A  = -__expf(A_log[d * DSTATE + s]);
    const float Dv = Dp[d];

    const float* dload = dT  + (size_t)(ch0 + c) * SEQ + s;
    const float* xload = xsT + (size_t)(ch0 + c) * SEQ + s;
    const float* zload = zT  + (size_t)(ch0 + c) * SEQ + s;
    const float* bload = Bp + (size_t)b * SEQ * DSTATE + (size_t)c * DSTATE + s;

    const int sc = tid & 15, sl = tid >> 4;

    float h = 0.f;
    for (int l0 = 0; l0 < SEQ; l0 += 16) {
        const int p = (l0 >> 4) & 1;
        sd[c][s] = dload[l0];
        sx[c][s] = xload[l0];
        sz[c][s] = zload[l0];
        sb[c][s] = bload[(size_t)l0 * DSTATE];
        __syncthreads();

        #pragma unroll
        for (int li = 0; li < 16; li++) {
            float dv  = sd[c][li];
            float xv  = sx[c][li];
            float bpv = sb[li][s];
            float dA  = __expf(dv * A);
            h = fmaf(dA, h, dv * xv * bpv);

            float v = h;
            v += __shfl_xor_sync(0xffffffffu, v, 1);
            v += __shfl_xor_sync(0xffffffffu, v, 2);
            v += __shfl_xor_sync(0xffffffffu, v, 4);
            v += __shfl_xor_sync(0xffffffffu, v, 8);

            if (s == 0) {
                float zv = sz[c][li];
                float sig = zv / (1.f + __expf(-zv));
                sy[p][c][li] = tf32f((v + xv * Dv) * sig);
            }
        }
        __syncthreads();

        yg[(size_t)(b * SEQ + l0 + sl) * DINNER + d0 + sc] = sy[p][sc][sl];
    }
}

// ---------------------------------------------------------------------------
extern "C" void kernel_launch(void* const* d_in, const int* in_sizes, int n_in,
                              void* d_out, int out_size)
{
    const float* x      = (const float*)d_in[0];
    const float* W_in   = (const float*)d_in[1];
    const float* conv_w = (const float*)d_in[2];
    const float* conv_b = (const float*)d_in[3];
    const float* W_x    = (const float*)d_in[4];
    const float* W_dt   = (const float*)d_in[5];
    const float* b_dt   = (const float*)d_in[6];
    const float* A_log  = (const float*)d_in[7];
    const float* D_par  = (const float*)d_in[8];
    const float* W_out  = (const float*)d_in[9];
    float* out = (float*)d_out;

    float *x32, *xraw, *xs, *bp, *yg, *WinT, *WdtT, *WoutT, *dT, *xsT, *zT;
    cudaGetSymbolAddress((void**)&x32,   g_x32);
    cudaGetSymbolAddress((void**)&xraw,  g_xraw);
    cudaGetSymbolAddress((void**)&xs,    g_xs);
    cudaGetSymbolAddress((void**)&bp,    g_Bp);
    cudaGetSymbolAddress((void**)&yg,    g_yg);
    cudaGetSymbolAddress((void**)&WinT,  g_WinT);
    cudaGetSymbolAddress((void**)&WdtT,  g_WdtT);
    cudaGetSymbolAddress((void**)&WoutT, g_WoutT);
    cudaGetSymbolAddress((void**)&dT,    g_dT);
    cudaGetSymbolAddress((void**)&xsT,   g_xsT);
    cudaGetSymbolAddress((void**)&zT,    g_zT);

    cudaFuncSetAttribute((const void*)gemm_tc<0>,
                         cudaFuncAttributeMaxDynamicSharedMemorySize, GT_SMEM);
    cudaFuncSetAttribute((const void*)gemm_tc<2>,
                         cudaFuncAttributeMaxDynamicSharedMemorySize, GT_SMEM);
    cudaFuncSetAttribute((const void*)gemm_tc<3>,
                         cudaFuncAttributeMaxDynamicSharedMemorySize, GT_SMEM);

    // 1) fused prep: weight transposes (tf32) + x truncation
    prep_k<<<14336, 256>>>(W_in, WinT, W_dt, WdtT, W_out, WoutT, x, x32);

    // 2) x @ W_in: cols 0..2047 -> xraw [l,d]; cols 2048..4095 -> zT [b,d,l]
    gemm_tc<2><<<dim3(16, MROWS/128), 512, GT_SMEM>>>(
        x32, WinT, xraw, zT, MROWS, 2*DINNER, DMODEL, DINNER, nullptr);

    // 3) tiled conv+silu -> xs [l,d] and xsT [b,d,l] (tf32)
    conv_t<<<dim3(DINNER/32, SEQ/32, BATCH), dim3(32, 8)>>>(xraw, conv_w, conv_b, xs, xsT);

    // 4) softplus(xs @ W_dt + b_dt) -> dT [b,d,l]   (launch slot 4 -> profiled)
    gemm_tc<3><<<dim3(8, MROWS/128), 512, GT_SMEM>>>(
        xs, WdtT, nullptr, dT, MROWS, DINNER, DINNER, DINNER, b_dt);

    // 5) Bp = (xs @ W_x)[:, 16:32]
    bp_k<<<MROWS / 16, 256>>>(xs, W_x, bp);

    // 6) selective scan + gating -> yg [l,d] (tf32)
    scan2_k<<<(BATCH * DINNER) / 16, 256>>>(dT, xsT, zT, bp, A_log, D_par, yg);

    // 7) out = yg @ W_out
    gemm_tc<0><<<dim3(DMODEL/256, MROWS/128), 512, GT_SMEM>>>(
        yg, WoutT, out, nullptr, MROWS, DMODEL, DINNER, DMODEL, nullptr);
}

// round 17
// speedup vs baseline: 1.1655x; 1.0475x over previous
#include <cuda_runtime.h>
#include <cuda_bf16.h>
#include <cstdint>

// Problem constants
#define BATCH   2
#define SEQ     2048
#define DMODEL  1024
#define DINNER  2048
#define DSTATE  16
#define DCONV   4
#define MROWS   (BATCH*SEQ)          // 4096

// Scratch (device globals; allocation is forbidden)
__device__ float g_x32[(size_t)MROWS * DMODEL];      // tf32-truncated x
__device__ float g_xraw[(size_t)MROWS * DINNER];     // pre-conv xs  [l,d]
__device__ float g_xs[(size_t)MROWS * DINNER];       // post conv+silu [l,d] (tf32)
__device__ float g_Bp[(size_t)MROWS * DSTATE];       // (xs@W_x)[:,16:32]
__device__ float g_yg[(size_t)MROWS * DINNER];       // gated scan output [l,d] (tf32)
__device__ float g_WinT[(size_t)(2*DINNER) * DMODEL];  // W_in^T  (tf32)
__device__ float g_WdtT[(size_t)DINNER * DINNER];      // W_dt^T  (tf32)
__device__ float g_WoutT[(size_t)DMODEL * DINNER];     // W_out^T (tf32)
__device__ float g_dT[(size_t)BATCH * DINNER * SEQ];   // delta^T [b,d,l]
__device__ float g_xsT[(size_t)BATCH * DINNER * SEQ];  // xs^T    [b,d,l]
__device__ float g_zT[(size_t)BATCH * DINNER * SEQ];   // z^T     [b,d,l]

// ---------------------------------------------------------------------------
__device__ __forceinline__ uint32_t f2tf32(float f) {
    uint32_t r;
    asm("cvt.rna.tf32.f32 %0, %1;" : "=r"(r) : "f"(f));
    return r;
}
__device__ __forceinline__ float tf32f(float f) { return __uint_as_float(f2tf32(f)); }

__device__ __forceinline__ uint32_t smem_u32(const void* p) {
    uint32_t a;
    asm("{ .reg .u64 t; cvta.to.shared.u64 t, %1; cvt.u32.u64 %0, t; }"
        : "=r"(a) : "l"(p));
    return a;
}

#define CP_ASYNC16(dst_u32, src_ptr) \
    asm volatile("cp.async.cg.shared.global [%0], [%1], 16;" \
        :: "r"(dst_u32), "l"(src_ptr) : "memory")
#define CP_COMMIT() asm volatile("cp.async.commit_group;" ::: "memory")
#define CP_WAIT(n)  asm volatile("cp.async.wait_group %0;" :: "n"(n) : "memory")

__device__ __forceinline__ void mma_tf32(float c[4],
    uint32_t a0, uint32_t a1, uint32_t a2, uint32_t a3,
    uint32_t b0, uint32_t b1)
{
    asm volatile(
        "mma.sync.aligned.m16n8k8.row.col.f32.tf32.tf32.f32 "
        "{%0,%1,%2,%3}, {%4,%5,%6,%7}, {%8,%9}, {%0,%1,%2,%3};"
        : "+f"(c[0]), "+f"(c[1]), "+f"(c[2]), "+f"(c[3])
        : "r"(a0), "r"(a1), "r"(a2), "r"(a3), "r"(b0), "r"(b1));
}

// ===========================================================================
// TF32 tensor-core GEMM: CTA tile 128x256, 512 thr = 16 warps as 2(M) x 8(N),
// warp tile 64x32, BK=64, cp.async double-buffered staging (inputs pre-tf32).
// MODE 0: plain write to C (ldc).
// MODE 2: bn<8 -> plain write into C (ldc); bn>=8 -> transposed to CT [b,d,l].
// MODE 3: softplus(v + bias[col]) then transposed write into CT.
// ===========================================================================
#define SSTRIDE 68                          // 64 k-words + 4 pad
#define AWORDS  (128 * SSTRIDE)             // 8704
#define BWORDS  (256 * SSTRIDE)             // 17408
#define BUFWORDS (AWORDS + BWORDS)          // 26112
#define GT_SMEM  (2 * BUFWORDS * 4)         // 208896 bytes (>= epilogue 67584)

template <int MODE>
__global__ void __launch_bounds__(512, 1) gemm_tc(
    const float* __restrict__ A, const float* __restrict__ Bt,
    float* __restrict__ C, float* __restrict__ CT,
    int M, int N, int K, int ldc, const float* __restrict__ bias)
{
    extern __shared__ uint32_t sbuf[];

    const int tid = threadIdx.x;
    const int wid = tid >> 5, lane = tid & 31;
    const int g  = lane >> 2;
    const int tg = lane & 3;
    const int wm = wid & 1;          // M slot (64 rows)
    const int wn = wid >> 1;         // N slot (32 cols), 0..7
    const int bm = blockIdx.y, bn = blockIdx.x;

    const float* Ab = A  + (size_t)(bm * 128) * K;
    const float* Bb = Bt + (size_t)(bn * 256) * K;

    const uint32_t sb0 = smem_u32(sbuf);

    float acc[4][4][4];
    #pragma unroll
    for (int i = 0; i < 4; i++)
        #pragma unroll
        for (int j = 0; j < 4; j++)
            #pragma unroll
            for (int f = 0; f < 4; f++) acc[i][j][f] = 0.f;

    const int nchunk = K / 64;

    {
        #pragma unroll
        for (int i = 0; i < 4; i++) {           // A: 128 rows x 16 quads
            int idx = tid + i * 512;
            int row = idx >> 4, q = idx & 15;
            CP_ASYNC16(sb0 + (uint32_t)(row * SSTRIDE + q * 4) * 4,
                       Ab + (size_t)row * K + q * 4);
        }
        #pragma unroll
        for (int i = 0; i < 8; i++) {           // B: 256 rows x 16 quads
            int idx = tid + i * 512;
            int row = idx >> 4, q = idx & 15;
            CP_ASYNC16(sb0 + (uint32_t)(AWORDS + row * SSTRIDE + q * 4) * 4,
                       Bb + (size_t)row * K + q * 4);
        }
        CP_COMMIT();
    }

    for (int c = 0; c < nchunk; c++) {
        if (c + 1 < nchunk) {
            const uint32_t base = sb0 + (uint32_t)(((c + 1) & 1) * BUFWORDS) * 4;
            const int k0n = (c + 1) * 64;
            #pragma unroll
            for (int i = 0; i < 4; i++) {
                int idx = tid + i * 512;
                int row = idx >> 4, q = idx & 15;
                CP_ASYNC16(base + (uint32_t)(row * SSTRIDE + q * 4) * 4,
                           Ab + (size_t)row * K + k0n + q * 4);
            }
            #pragma unroll
            for (int i = 0; i < 8; i++) {
                int idx = tid + i * 512;
                int row = idx >> 4, q = idx & 15;
                CP_ASYNC16(base + (uint32_t)(AWORDS + row * SSTRIDE + q * 4) * 4,
                           Bb + (size_t)row * K + k0n + q * 4);
            }
            CP_COMMIT();
            CP_WAIT(1);
        } else {
            CP_WAIT(0);
        }
        __syncthreads();

        const uint32_t* As = sbuf + (c & 1) * BUFWORDS;
        const uint32_t* Bs = As + AWORDS;
        #pragma unroll
        for (int ks = 0; ks < 8; ks++) {
            const int k0 = ks * 8;
            uint32_t af[4][4];
            uint32_t bf[4][2];
            #pragma unroll
            for (int mi = 0; mi < 4; mi++) {
                int mbase = wm * 64 + mi * 16;
                af[mi][0] = As[(mbase + g)     * SSTRIDE + k0 + tg];
                af[mi][1] = As[(mbase + g + 8) * SSTRIDE + k0 + tg];
                af[mi][2] = As[(mbase + g)     * SSTRIDE + k0 + tg + 4];
                af[mi][3] = As[(mbase + g + 8) * SSTRIDE + k0 + tg + 4];
            }
            #pragma unroll
            for (int ni = 0; ni < 4; ni++) {
                int nbase = wn * 32 + ni * 8;
                bf[ni][0] = Bs[(nbase + g) * SSTRIDE + k0 + tg];
                bf[ni][1] = Bs[(nbase + g) * SSTRIDE + k0 + tg + 4];
            }
            #pragma unroll
            for (int mi = 0; mi < 4; mi++)
                #pragma unroll
                for (int ni = 0; ni < 4; ni++)
                    mma_tf32(acc[mi][ni], af[mi][0], af[mi][1], af[mi][2], af[mi][3],
                             bf[ni][0], bf[ni][1]);
        }
        __syncthreads();
    }

    const bool trans = (MODE == 3) || (MODE == 2 && bn >= 8);

    if (!trans) {
        #pragma unroll
        for (int mi = 0; mi < 4; mi++) {
            #pragma unroll
            for (int ni = 0; ni < 4; ni++) {
                int row0 = bm * 128 + wm * 64 + mi * 16 + g;
                int col  = bn * 256 + wn * 32 + ni * 8 + 2 * tg;
                *(float2*)(C + (size_t)row0 * ldc + col) =
                    make_float2(acc[mi][ni][0], acc[mi][ni][1]);
                *(float2*)(C + (size_t)(row0 + 8) * ldc + col) =
                    make_float2(acc[mi][ni][2], acc[mi][ni][3]);
            }
        }
    } else {
        float* st = (float*)sbuf;
        const int dbase = (MODE == 2) ? (bn - 8) * 256 : bn * 256;
        const int bz = bm >> 4;
        const int l0 = (bm & 15) * 128;
        #pragma unroll
        for (int half = 0; half < 2; half++) {
            if ((wn >> 2) == half) {
                #pragma unroll
                for (int mi = 0; mi < 4; mi++) {
                    #pragma unroll
                    for (int ni = 0; ni < 4; ni++) {
                        int rl = wm * 64 + mi * 16 + g;
                        int clg = wn * 32 + ni * 8 + 2 * tg;
                        int cl  = clg - half * 128;
                        float v0 = acc[mi][ni][0], v1 = acc[mi][ni][1];
                        float v2 = acc[mi][ni][2], v3 = acc[mi][ni][3];
                        if (MODE == 3) {
                            int col = bn * 256 + clg;
                            float b0 = bias[col], b1 = bias[col + 1];
                            v0 += b0; v1 += b1; v2 += b0; v3 += b1;
                            v0 = (v0 > 20.f) ? v0 : log1pf(__expf(v0));
                            v1 = (v1 > 20.f) ? v1 : log1pf(__expf(v1));
                            v2 = (v2 > 20.f) ? v2 : log1pf(__expf(v2));
                            v3 = (v3 > 20.f) ? v3 : log1pf(__expf(v3));
                        }
                        st[(cl)     * 132 + rl]     = v0;
                        st[(cl + 1) * 132 + rl]     = v1;
                        st[(cl)     * 132 + rl + 8] = v2;
                        st[(cl + 1) * 132 + rl + 8] = v3;
                    }
                }
            }
            __syncthreads();
            #pragma unroll
            for (int i = 0; i < 8; i++) {
                int idx = tid + i * 512;
                int dl = idx >> 5;
                int c4 = idx & 31;
                float4 v = *(float4*)&st[dl * 132 + c4 * 4];
                *(float4*)&CT[((size_t)bz * DINNER + dbase + half * 128 + dl) * SEQ
                              + l0 + c4 * 4] = v;
            }
            __syncthreads();
        }
    }
}

// ---------------------------------------------------------------------------
// Fused prep: weight transposes (+tf32), x truncation, Bp zeroing.
// tiles: [0,4096) Win | [4096,8192) Wdt | [8192,10240) Wout |
//        [10240,14336) trunc x | [14336,14400) zero Bp
// ---------------------------------------------------------------------------
__device__ __forceinline__ void transpose_tile(
    const float* __restrict__ in, float* __restrict__ out,
    int R, int C, int xt, int yt, int tid)
{
    __shared__ float t[32][33];
    const int tx = tid & 31, ty = tid >> 5;
    const int bx = xt * 32, by = yt * 32;
    #pragma unroll
    for (int i = 0; i < 32; i += 8)
        t[ty + i][tx] = in[(size_t)(by + ty + i) * C + bx + tx];
    __syncthreads();
    #pragma unroll
    for (int i = 0; i < 32; i += 8)
        out[(size_t)(bx + ty + i) * R + by + tx] = tf32f(t[tx][ty + i]);
}

__global__ __launch_bounds__(256) void prep_k(
    const float* __restrict__ W_in,  float* __restrict__ WinT,
    const float* __restrict__ W_dt,  float* __restrict__ WdtT,
    const float* __restrict__ W_out, float* __restrict__ WoutT,
    const float* __restrict__ x,     float* __restrict__ x32,
    float* __restrict__ Bp)
{
    const int b = blockIdx.x;
    const int tid = threadIdx.x;
    if (b < 4096) {
        transpose_tile(W_in, WinT, DMODEL, 2 * DINNER, b % 128, b / 128, tid);
    } else if (b < 8192) {
        int t = b - 4096;
        transpose_tile(W_dt, WdtT, DINNER, DINNER, t % 64, t / 64, tid);
    } else if (b < 10240) {
        int t = b - 8192;
        transpose_tile(W_out, WoutT, DINNER, DMODEL, t % 32, t / 32, tid);
    } else if (b < 14336) {
        int i = (b - 10240) * 256 + tid;
        float4 v = ((const float4*)x)[i];
        v.x = tf32f(v.x); v.y = tf32f(v.y); v.z = tf32f(v.z); v.w = tf32f(v.w);
        ((float4*)x32)[i] = v;
    } else {                              // zero Bp: 65536 floats = 16384 float4
        int i = (b - 14336) * 256 + tid;
        ((float4*)Bp)[i] = make_float4(0.f, 0.f, 0.f, 0.f);
    }
}

// ---------------------------------------------------------------------------
// Tiled depthwise causal conv (width 4) + bias + silu (tf32 output), fused
// with partial Bp accumulation: Bp[row,s] += sum_{d in tile} xs[row,d]*Wx[d,16+s].
// ---------------------------------------------------------------------------
__global__ __launch_bounds__(256) void conv_t(
    const float* __restrict__ xraw, const float* __restrict__ cw,
    const float* __restrict__ cb, const float* __restrict__ Wx,
    float* __restrict__ xs, float* __restrict__ xsT, float* __restrict__ Bp)
{
    __shared__ float sxin[35][33];
    __shared__ float sy[32][33];
    __shared__ float swx[32][16];
    const int tid = threadIdx.x + threadIdx.y * 32;
    const int tx = threadIdx.x, ty = threadIdx.y;
    const int d0 = blockIdx.x * 32, l0 = blockIdx.y * 32, b = blockIdx.z;

    #pragma unroll
    for (int i = 0; i < 5; i++) {
        int r = ty + i * 8;
        if (r < 35) {
            int l = l0 + r - 3;
            float v = (l >= 0) ? xraw[((size_t)(b * SEQ + l)) * DINNER + d0 + tx] : 0.f;
            sxin[r][tx] = v;
        }
    }
    #pragma unroll
    for (int i = 0; i < 2; i++) {
        int idx = tid + i * 256;       // 0..511
        int dd = idx >> 4, s = idx & 15;
        swx[dd][s] = Wx[(size_t)(d0 + dd) * (2 * DSTATE) + DSTATE + s];
    }
    __syncthreads();

    const int d = d0 + tx;
    const float w0 = cw[d * 4 + 0], w1 = cw[d * 4 + 1];
    const float w2 = cw[d * 4 + 2], w3 = cw[d * 4 + 3];
    const float bb = cb[d];

    #pragma unroll
    for (int i = 0; i < 4; i++) {
        int r = ty + i * 8;
        float a = bb;
        a = fmaf(w0, sxin[r][tx],     a);
        a = fmaf(w1, sxin[r + 1][tx], a);
        a = fmaf(w2, sxin[r + 2][tx], a);
        a = fmaf(w3, sxin[r + 3][tx], a);
        float val = tf32f(a / (1.f + __expf(-a)));
        sy[r][tx] = val;
        xs[((size_t)(b * SEQ + l0 + r)) * DINNER + d] = val;
    }
    __syncthreads();

    #pragma unroll
    for (int i = 0; i < 4; i++) {
        int dl = ty + i * 8;
        xsT[((size_t)(b * DINNER + d0 + dl)) * SEQ + l0 + tx] = sy[tx][dl];
    }

    // partial Bp for this (l-tile, d-tile): 32l x 16s outputs, 2 per thread
    #pragma unroll
    for (int half = 0; half < 2; half++) {
        int l = (tid >> 4) + half * 16;    // 0..31
        int s = tid & 15;
        float acc = 0.f;
        #pragma unroll
        for (int dd = 0; dd < 32; dd++)
            acc = fmaf(sy[l][dd], swx[dd][s], acc);
        atomicAdd(&Bp[(size_t)(b * SEQ + l0 + l) * DSTATE + s], acc);
    }
}

// ---------------------------------------------------------------------------
// Selective scan v2: channel-major inputs, 16-step smem chunks, 2 syncs/chunk.
// ---------------------------------------------------------------------------
__global__ __launch_bounds__(256) void scan2_k(
    const float* __restrict__ dT, const float* __restrict__ xsT,
    const float* __restrict__ zT, const float* __restrict__ Bp,
    const float* __restrict__ A_log, const float* __restrict__ Dp,
    float* __restrict__ yg)
{
    __shared__ float sd[16][17], sx[16][17], sz[16][17];
    __shared__ float sy[2][16][17];
    __shared__ float sb[16][16];

    const int tid = threadIdx.x;
    const int c = tid >> 4;
    const int s = tid & 15;
    const int ch0 = blockIdx.x * 16;
    const int ch = ch0 + c;
    const int b = ch >> 11;
    const int d = ch & (DINNER - 1);
    const int d0 = ch0 & (DINNER - 1);

    const float A  = -__expf(A_log[d * DSTATE + s]);
    const float Dv = Dp[d];

    const float* dload = dT  + (size_t)(ch0 + c) * SEQ + s;
    const float* xload = xsT + (size_t)(ch0 + c) * SEQ + s;
    const float* zload = zT  + (size_t)(ch0 + c) * SEQ + s;
    const float* bload = Bp + (size_t)b * SEQ * DSTATE + (size_t)c * DSTATE + s;

    const int sc = tid & 15, sl = tid >> 4;

    float h = 0.f;
    for (int l0 = 0; l0 < SEQ; l0 += 16) {
        const int p = (l0 >> 4) & 1;
        sd[c][s] = dload[l0];
        sx[c][s] = xload[l0];
        sz[c][s] = zload[l0];
        sb[c][s] = bload[(size_t)l0 * DSTATE];
        __syncthreads();

        #pragma unroll
        for (int li = 0; li < 16; li++) {
            float dv  = sd[c][li];
            float xv  = sx[c][li];
            float bpv = sb[li][s];
            float dA  = __expf(dv * A);
            h = fmaf(dA, h, dv * xv * bpv);

            float v = h;
            v += __shfl_xor_sync(0xffffffffu, v, 1);
            v += __shfl_xor_sync(0xffffffffu, v, 2);
            v += __shfl_xor_sync(0xffffffffu, v, 4);
            v += __shfl_xor_sync(0xffffffffu, v, 8);

            if (s == 0) {
                float zv = sz[c][li];
                float sig = zv / (1.f + __expf(-zv));
                sy[p][c][li] = tf32f((v + xv * Dv) * sig);
            }
        }
        __syncthreads();

        yg[(size_t)(b * SEQ + l0 + sl) * DINNER + d0 + sc] = sy[p][sc][sl];
    }
}

// ---------------------------------------------------------------------------
extern "C" void kernel_launch(void* const* d_in, const int* in_sizes, int n_in,
                              void* d_out, int out_size)
{
    const float* x      = (const float*)d_in[0];
    const float* W_in   = (const float*)d_in[1];
    const float* conv_w = (const float*)d_in[2];
    const float* conv_b = (const float*)d_in[3];
    const float* W_x    = (const float*)d_in[4];
    const float* W_dt   = (const float*)d_in[5];
    const float* b_dt   = (const float*)d_in[6];
    const float* A_log  = (const float*)d_in[7];
    const float* D_par  = (const float*)d_in[8];
    const float* W_out  = (const float*)d_in[9];
    float* out = (float*)d_out;

    float *x32, *xraw, *xs, *bp, *yg, *WinT, *WdtT, *WoutT, *dT, *xsT, *zT;
    cudaGetSymbolAddress((void**)&x32,   g_x32);
    cudaGetSymbolAddress((void**)&xraw,  g_xraw);
    cudaGetSymbolAddress((void**)&xs,    g_xs);
    cudaGetSymbolAddress((void**)&bp,    g_Bp);
    cudaGetSymbolAddress((void**)&yg,    g_yg);
    cudaGetSymbolAddress((void**)&WinT,  g_WinT);
    cudaGetSymbolAddress((void**)&WdtT,  g_WdtT);
    cudaGetSymbolAddress((void**)&WoutT, g_WoutT);
    cudaGetSymbolAddress((void**)&dT,    g_dT);
    cudaGetSymbolAddress((void**)&xsT,   g_xsT);
    cudaGetSymbolAddress((void**)&zT,    g_zT);

    cudaFuncSetAttribute((const void*)gemm_tc<0>,
                         cudaFuncAttributeMaxDynamicSharedMemorySize, GT_SMEM);
    cudaFuncSetAttribute((const void*)gemm_tc<2>,
                         cudaFuncAttributeMaxDynamicSharedMemorySize, GT_SMEM);
    cudaFuncSetAttribute((const void*)gemm_tc<3>,
                         cudaFuncAttributeMaxDynamicSharedMemorySize, GT_SMEM);

    // 1) fused prep: weight transposes (tf32) + x truncation + Bp zeroing
    prep_k<<<14400, 256>>>(W_in, WinT, W_dt, WdtT, W_out, WoutT, x, x32, bp);

    // 2) x @ W_in: cols 0..2047 -> xraw [l,d]; cols 2048..4095 -> zT [b,d,l]
    gemm_tc<2><<<dim3(16, MROWS/128), 512, GT_SMEM>>>(
        x32, WinT, xraw, zT, MROWS, 2*DINNER, DMODEL, DINNER, nullptr);

    // 3) conv+silu -> xs, xsT; fused partial Bp accumulation
    conv_t<<<dim3(DINNER/32, SEQ/32, BATCH), dim3(32, 8)>>>(
        xraw, conv_w, conv_b, W_x, xs, xsT, bp);

    // 4) softplus(xs @ W_dt + b_dt) -> dT [b,d,l]   (launch slot 4 -> profiled)
    gemm_tc<3><<<dim3(8, MROWS/128), 512, GT_SMEM>>>(
        xs, WdtT, nullptr, dT, MROWS, DINNER, DINNER, DINNER, b_dt);

    // 5) selective scan + gating -> yg [l,d] (tf32)
    scan2_k<<<(BATCH * DINNER) / 16, 256>>>(dT, xsT, zT, bp, A_log, D_par, yg);

    // 6) out = yg @ W_out
    gemm_tc<0><<<dim3(DMODEL/256, MROWS/128), 512, GT_SMEM>>>(
        yg, WoutT, out, nullptr, MROWS, DMODEL, DINNER, DMODEL, nullptr);
}